// round 1
// baseline (speedup 1.0000x reference)
#include <cuda_runtime.h>
#include <cstdint>

// Problem constants
#define BATCH 64
#define CHN   64
#define LSEQ  512
#define INTER 128
#define DCP   256
#define DDE   1024
#define KSEL  16
#define SCALE 0.05f

// Scratch (device globals; no runtime allocation)
__device__ float g_h1[(size_t)CHN * LSEQ * DCP];      // (C*L, 256)  after GEMM1+relu
__device__ float g_mapT[(size_t)CHN * DCP * LSEQ];    // (C, 256, 512) after GEMM2 (transposed store)
__device__ float g_h2[(size_t)CHN * DCP * DDE];       // (C*256, 1024) after GEMM3+relu
__device__ float g_mapst[(size_t)CHN * DCP * LSEQ];   // (C*256, 512) after GEMM4

// ---------------------------------------------------------------------------
// Tiled fp32 GEMM: C = act(A(MxK) @ B(KxN) + bias(N))
// BM=BN=64, BK=16, 256 threads, 4x4 micro-tile per thread.
// SWAP: store out[m,n] to g[(m/512)*256*512 + n*512 + (m%512)] (the (C,L,Dcp)->(C,Dcp,L) swap)
// ---------------------------------------------------------------------------
#define BM 64
#define BN 64
#define BK 16

template<bool RELU, bool SWAP>
__global__ __launch_bounds__(256) void gemm_k(const float* __restrict__ A,
                                              const float* __restrict__ B,
                                              const float* __restrict__ bias,
                                              float* __restrict__ C,
                                              int M, int N, int K)
{
    __shared__ float As[BK][BM + 1];
    __shared__ float Bs[BK][BN];

    const int t  = threadIdx.x;
    const int tx = t & 15;         // 0..15 -> n micro
    const int ty = t >> 4;         // 0..15 -> m micro
    const int bm = blockIdx.y * BM;
    const int bn = blockIdx.x * BN;

    const int arow = t >> 2;            // 0..63
    const int acol = (t & 3) * 4;       // 0,4,8,12
    const int brow = t >> 4;            // 0..15
    const int bcol = (t & 15) * 4;      // 0..60

    const float* Aptr = A + (size_t)(bm + arow) * K + acol;
    const float* Bptr = B + (size_t)brow * N + bn + bcol;

    float acc[4][4] = {};

    for (int kt = 0; kt < K; kt += BK) {
        float4 av = *(const float4*)(Aptr + kt);
        float4 bv = *(const float4*)(Bptr + (size_t)kt * N);
        As[acol + 0][arow] = av.x;
        As[acol + 1][arow] = av.y;
        As[acol + 2][arow] = av.z;
        As[acol + 3][arow] = av.w;
        *(float4*)&Bs[brow][bcol] = bv;
        __syncthreads();

        #pragma unroll
        for (int k = 0; k < BK; k++) {
            float a[4], b[4];
            #pragma unroll
            for (int i = 0; i < 4; i++) a[i] = As[k][ty * 4 + i];
            #pragma unroll
            for (int j = 0; j < 4; j++) b[j] = Bs[k][tx * 4 + j];
            #pragma unroll
            for (int i = 0; i < 4; i++)
                #pragma unroll
                for (int j = 0; j < 4; j++)
                    acc[i][j] = fmaf(a[i], b[j], acc[i][j]);
        }
        __syncthreads();
    }

    #pragma unroll
    for (int i = 0; i < 4; i++) {
        const int m = bm + ty * 4 + i;
        #pragma unroll
        for (int j = 0; j < 4; j++) {
            const int n = bn + tx * 4 + j;
            float v = acc[i][j] + bias[n];
            if (RELU) v = fmaxf(v, 0.0f);
            if (SWAP) {
                const int c = m >> 9;        // m / 512
                const int l = m & 511;       // m % 512
                C[((size_t)c * DCP + n) * LSEQ + l] = v;
            } else {
                C[(size_t)m * N + n] = v;
            }
        }
    }
}

// ---------------------------------------------------------------------------
// Fused tail: gather K rows, L1 scores, softmax, weighted sum, gated blend.
// One block per (b, c). 256 threads.
// ---------------------------------------------------------------------------
__global__ __launch_bounds__(256) void fuse_k(const float* __restrict__ x_loc,
                                              const float* __restrict__ map_st,
                                              const int*   __restrict__ indices,
                                              const float* __restrict__ lamda1,
                                              const float* __restrict__ lamda2,
                                              float* __restrict__ out)
{
    __shared__ float xs[LSEQ];
    __shared__ float ms[KSEL][LSEQ];
    __shared__ float warpsum[KSEL][8];
    __shared__ float wgt[KSEL];

    const int bc = blockIdx.x;        // b*CHN + c
    const int c  = bc & (CHN - 1);
    const int t  = threadIdx.x;

    const float* xrow = x_loc + (size_t)bc * LSEQ;
    for (int i = t; i < LSEQ; i += 256) xs[i] = xrow[i];

    #pragma unroll
    for (int k = 0; k < KSEL; k++) {
        const int d = indices[bc * KSEL + k];
        const float* mrow = map_st + ((size_t)c * DCP + d) * LSEQ;
        for (int i = t; i < LSEQ; i += 256) ms[k][i] = mrow[i];
    }
    __syncthreads();

    // per-thread partial L1 sums for all K
    float part[KSEL];
    #pragma unroll
    for (int k = 0; k < KSEL; k++) part[k] = 0.0f;
    for (int i = t; i < LSEQ; i += 256) {
        const float x = xs[i];
        #pragma unroll
        for (int k = 0; k < KSEL; k++) part[k] += fabsf(x - ms[k][i]);
    }

    const int lane = t & 31, w = t >> 5;
    #pragma unroll
    for (int k = 0; k < KSEL; k++) {
        float v = part[k];
        #pragma unroll
        for (int off = 16; off > 0; off >>= 1)
            v += __shfl_down_sync(0xffffffffu, v, off);
        if (lane == 0) warpsum[k][w] = v;
    }
    __syncthreads();

    if (t < KSEL) {
        float s = 0.0f;
        #pragma unroll
        for (int ww = 0; ww < 8; ww++) s += warpsum[t][ww];
        float score = -s * SCALE;
        float mx = score;
        #pragma unroll
        for (int off = 8; off > 0; off >>= 1)
            mx = fmaxf(mx, __shfl_xor_sync(0x0000ffffu, mx, off));
        float e  = expf(score - mx);
        float se = e;
        #pragma unroll
        for (int off = 8; off > 0; off >>= 1)
            se += __shfl_xor_sync(0x0000ffffu, se, off);
        wgt[t] = e / se;
    }
    __syncthreads();

    const float s1 = 1.0f / (1.0f + expf(-lamda1[c]));
    float* orow = out + (size_t)bc * LSEQ;
    for (int i = t; i < LSEQ; i += 256) {
        float g = 0.0f;
        #pragma unroll
        for (int k = 0; k < KSEL; k++) g = fmaf(wgt[k], ms[k][i], g);
        const float s2  = 1.0f / (1.0f + expf(-lamda2[i]));
        const float lam = s1 * s2;
        orow[i] = g * lam + xs[i] * (1.0f - lam);
    }
}

// ---------------------------------------------------------------------------
static float* symaddr(const void* sym)
{
    void* p = nullptr;
    cudaGetSymbolAddress(&p, sym);
    return (float*)p;
}

extern "C" void kernel_launch(void* const* d_in, const int* in_sizes, int n_in,
                              void* d_out, int out_size)
{
    const float* x_loc   = (const float*)d_in[0];
    const float* map_raw = (const float*)d_in[1];
    const float* cp_w1   = (const float*)d_in[2];
    const float* cp_b1   = (const float*)d_in[3];
    const float* cp_w2   = (const float*)d_in[4];
    const float* cp_b2   = (const float*)d_in[5];
    const float* de_w1   = (const float*)d_in[6];
    const float* de_b1   = (const float*)d_in[7];
    const float* de_w2   = (const float*)d_in[8];
    const float* de_b2   = (const float*)d_in[9];
    const float* lamda1  = (const float*)d_in[10];
    const float* lamda2  = (const float*)d_in[11];
    const int*   indices = (const int*)d_in[12];
    float* out = (float*)d_out;

    float* h1    = symaddr(g_h1);
    float* mapT  = symaddr(g_mapT);
    float* h2    = symaddr(g_h2);
    float* mapst = symaddr(g_mapst);

    const int M1 = CHN * LSEQ;   // 32768
    const int M3 = CHN * DCP;    // 16384

    // GEMM1: (32768,128)@(128,256) + b, relu -> h1
    gemm_k<true,  false><<<dim3(DCP / BN, M1 / BM), 256>>>(map_raw, cp_w1, cp_b1, h1, M1, DCP, INTER);
    // GEMM2: (32768,256)@(256,256) + b -> mapT (transposed store to (C,Dcp,L))
    gemm_k<false, true ><<<dim3(DCP / BN, M1 / BM), 256>>>(h1, cp_w2, cp_b2, mapT, M1, DCP, DCP);
    // GEMM3: (16384,512)@(512,1024) + b, relu -> h2
    gemm_k<true,  false><<<dim3(DDE / BN, M3 / BM), 256>>>(mapT, de_w1, de_b1, h2, M3, DDE, LSEQ);
    // GEMM4: (16384,1024)@(1024,512) + b -> mapst
    gemm_k<false, false><<<dim3(LSEQ / BN, M3 / BM), 256>>>(h2, de_w2, de_b2, mapst, M3, LSEQ, DDE);
    // Fused gather/score/softmax/blend
    fuse_k<<<BATCH * CHN, 256>>>(x_loc, mapst, indices, lamda1, lamda2, out);
}

// round 2
// speedup vs baseline: 2.6972x; 2.6972x over previous
#include <cuda_runtime.h>
#include <cstdint>

// Problem constants
#define BATCH 64
#define CHN   64
#define LSEQ  512
#define INTER 128
#define DCP   256
#define DDE   1024
#define KSEL  16
#define SCALE 0.05f

// Scratch (device globals; no runtime allocation)
__device__ float g_h1[(size_t)CHN * LSEQ * DCP];      // (C*L, 256)  after GEMM1+relu
__device__ float g_mapT[(size_t)CHN * DCP * LSEQ];    // (C, 256, 512) after GEMM2 (transposed store)
__device__ float g_h2[(size_t)CHN * DCP * DDE];       // (C*256, 1024) after GEMM3+relu
__device__ float g_mapst[(size_t)CHN * DCP * LSEQ];   // (C*256, 512) after GEMM4

// ---------------------------------------------------------------------------
// TF32 tensor-core GEMM: C = act(A(MxK) @ B(KxN) + bias(N))
// BM=BN=128, BK=16, 256 threads = 8 warps in 4(M) x 2(N); warp tile 32x64.
// mma.sync.aligned.m16n8k8.row.col.f32.tf32.tf32.f32
// Smem stored k-major with +8 padding -> conflict-free fragment loads.
// ---------------------------------------------------------------------------
#define BM 128
#define BN 128
#define BK 16

__device__ __forceinline__ uint32_t f2tf(float f) {
    uint32_t r;
    asm("cvt.rna.tf32.f32 %0, %1;" : "=r"(r) : "f"(f));
    return r;
}

template<bool RELU, bool SWAP>
__global__ __launch_bounds__(256) void gemm_tc(const float* __restrict__ A,
                                               const float* __restrict__ B,
                                               const float* __restrict__ bias,
                                               float* __restrict__ C,
                                               int M, int N, int K)
{
    __shared__ uint32_t As[BK][BM + 8];   // [k][m]
    __shared__ uint32_t Bs[BK][BN + 8];   // [k][n]

    const int t    = threadIdx.x;
    const int lane = t & 31;
    const int w    = t >> 5;
    const int wm   = (w & 3) * 32;        // warp m offset in tile
    const int wn   = (w >> 2) * 64;       // warp n offset in tile
    const int bm   = blockIdx.y * BM;
    const int bn   = blockIdx.x * BN;

    // staging assignments
    const int am  = t >> 2;               // 0..63  (A row, +64 for second)
    const int ak  = (t & 3) * 4;          // 0,4,8,12
    const int bk  = t >> 5;               // 0..7   (B row, +8 for second)
    const int bn4 = (t & 31) * 4;         // 0..124

    const float* Ag = A + (size_t)(bm + am) * K + ak;
    const float* Bg = B + (size_t)bk * N + bn + bn4;

    float4 ra0 = *(const float4*)(Ag);
    float4 ra1 = *(const float4*)(Ag + (size_t)64 * K);
    float4 rb0 = *(const float4*)(Bg);
    float4 rb1 = *(const float4*)(Bg + (size_t)8 * N);

    float acc[2][8][4];
    #pragma unroll
    for (int i = 0; i < 2; i++)
        #pragma unroll
        for (int j = 0; j < 8; j++)
            #pragma unroll
            for (int q = 0; q < 4; q++) acc[i][j][q] = 0.0f;

    const int ntiles = K / BK;
    for (int kt = 0; kt < ntiles; kt++) {
        // stage regs -> smem (with tf32 rounding)
        As[ak + 0][am]      = f2tf(ra0.x);
        As[ak + 1][am]      = f2tf(ra0.y);
        As[ak + 2][am]      = f2tf(ra0.z);
        As[ak + 3][am]      = f2tf(ra0.w);
        As[ak + 0][am + 64] = f2tf(ra1.x);
        As[ak + 1][am + 64] = f2tf(ra1.y);
        As[ak + 2][am + 64] = f2tf(ra1.z);
        As[ak + 3][am + 64] = f2tf(ra1.w);
        {
            uint4 v0 = make_uint4(f2tf(rb0.x), f2tf(rb0.y), f2tf(rb0.z), f2tf(rb0.w));
            uint4 v1 = make_uint4(f2tf(rb1.x), f2tf(rb1.y), f2tf(rb1.z), f2tf(rb1.w));
            *(uint4*)&Bs[bk][bn4]     = v0;
            *(uint4*)&Bs[bk + 8][bn4] = v1;
        }
        __syncthreads();

        // prefetch next tile
        if (kt + 1 < ntiles) {
            ra0 = *(const float4*)(Ag + (kt + 1) * BK);
            ra1 = *(const float4*)(Ag + (size_t)64 * K + (kt + 1) * BK);
            rb0 = *(const float4*)(Bg + (size_t)(kt + 1) * BK * N);
            rb1 = *(const float4*)(Bg + (size_t)((kt + 1) * BK + 8) * N);
        }

        // compute: 2 k-steps of 8
        #pragma unroll
        for (int ks = 0; ks < 2; ks++) {
            const int kb = ks * 8;
            uint32_t af[2][4];
            #pragma unroll
            for (int mi = 0; mi < 2; mi++) {
                const int r0 = wm + mi * 16 + (lane >> 2);
                const int c0 = kb + (lane & 3);
                af[mi][0] = As[c0][r0];
                af[mi][1] = As[c0][r0 + 8];
                af[mi][2] = As[c0 + 4][r0];
                af[mi][3] = As[c0 + 4][r0 + 8];
            }
            #pragma unroll
            for (int ni = 0; ni < 8; ni++) {
                const int nn = wn + ni * 8 + (lane >> 2);
                const uint32_t b0 = Bs[kb + (lane & 3)][nn];
                const uint32_t b1 = Bs[kb + (lane & 3) + 4][nn];
                #pragma unroll
                for (int mi = 0; mi < 2; mi++) {
                    asm volatile(
                        "mma.sync.aligned.m16n8k8.row.col.f32.tf32.tf32.f32 "
                        "{%0,%1,%2,%3}, {%4,%5,%6,%7}, {%8,%9}, {%0,%1,%2,%3};"
                        : "+f"(acc[mi][ni][0]), "+f"(acc[mi][ni][1]),
                          "+f"(acc[mi][ni][2]), "+f"(acc[mi][ni][3])
                        : "r"(af[mi][0]), "r"(af[mi][1]), "r"(af[mi][2]), "r"(af[mi][3]),
                          "r"(b0), "r"(b1));
                }
            }
        }
        __syncthreads();
    }

    // epilogue: c0,c1 -> (row, col), (row, col+1); c2,c3 -> (row+8, ...)
    #pragma unroll
    for (int mi = 0; mi < 2; mi++) {
        const int r = bm + wm + mi * 16 + (lane >> 2);
        #pragma unroll
        for (int ni = 0; ni < 8; ni++) {
            const int col = bn + wn + ni * 8 + 2 * (lane & 3);
            const float bv0 = bias[col];
            const float bv1 = bias[col + 1];
            #pragma unroll
            for (int h = 0; h < 2; h++) {
                const int m = r + h * 8;
                float v0 = acc[mi][ni][h * 2 + 0] + bv0;
                float v1 = acc[mi][ni][h * 2 + 1] + bv1;
                if (RELU) { v0 = fmaxf(v0, 0.0f); v1 = fmaxf(v1, 0.0f); }
                if (SWAP) {
                    const int c = m >> 9;      // m / 512
                    const int l = m & 511;     // m % 512
                    C[((size_t)c * DCP + col) * LSEQ + l]     = v0;
                    C[((size_t)c * DCP + col + 1) * LSEQ + l] = v1;
                } else {
                    *(float2*)&C[(size_t)m * N + col] = make_float2(v0, v1);
                }
            }
        }
    }
}

// ---------------------------------------------------------------------------
// Fused tail: gather K rows, L1 scores, softmax, weighted sum, gated blend.
// One block per (b, c). 256 threads.
// ---------------------------------------------------------------------------
__global__ __launch_bounds__(256) void fuse_k(const float* __restrict__ x_loc,
                                              const float* __restrict__ map_st,
                                              const int*   __restrict__ indices,
                                              const float* __restrict__ lamda1,
                                              const float* __restrict__ lamda2,
                                              float* __restrict__ out)
{
    __shared__ float xs[LSEQ];
    __shared__ float ms[KSEL][LSEQ];
    __shared__ float warpsum[KSEL][8];
    __shared__ float wgt[KSEL];

    const int bc = blockIdx.x;        // b*CHN + c
    const int c  = bc & (CHN - 1);
    const int t  = threadIdx.x;

    const float* xrow = x_loc + (size_t)bc * LSEQ;
    for (int i = t; i < LSEQ; i += 256) xs[i] = xrow[i];

    #pragma unroll
    for (int k = 0; k < KSEL; k++) {
        const int d = indices[bc * KSEL + k];
        const float* mrow = map_st + ((size_t)c * DCP + d) * LSEQ;
        for (int i = t; i < LSEQ; i += 256) ms[k][i] = mrow[i];
    }
    __syncthreads();

    float part[KSEL];
    #pragma unroll
    for (int k = 0; k < KSEL; k++) part[k] = 0.0f;
    for (int i = t; i < LSEQ; i += 256) {
        const float x = xs[i];
        #pragma unroll
        for (int k = 0; k < KSEL; k++) part[k] += fabsf(x - ms[k][i]);
    }

    const int lane = t & 31, w = t >> 5;
    #pragma unroll
    for (int k = 0; k < KSEL; k++) {
        float v = part[k];
        #pragma unroll
        for (int off = 16; off > 0; off >>= 1)
            v += __shfl_down_sync(0xffffffffu, v, off);
        if (lane == 0) warpsum[k][w] = v;
    }
    __syncthreads();

    if (t < KSEL) {
        float s = 0.0f;
        #pragma unroll
        for (int ww = 0; ww < 8; ww++) s += warpsum[t][ww];
        float score = -s * SCALE;
        float mx = score;
        #pragma unroll
        for (int off = 8; off > 0; off >>= 1)
            mx = fmaxf(mx, __shfl_xor_sync(0x0000ffffu, mx, off));
        float e  = expf(score - mx);
        float se = e;
        #pragma unroll
        for (int off = 8; off > 0; off >>= 1)
            se += __shfl_xor_sync(0x0000ffffu, se, off);
        wgt[t] = e / se;
    }
    __syncthreads();

    const float s1 = 1.0f / (1.0f + expf(-lamda1[c]));
    float* orow = out + (size_t)bc * LSEQ;
    for (int i = t; i < LSEQ; i += 256) {
        float g = 0.0f;
        #pragma unroll
        for (int k = 0; k < KSEL; k++) g = fmaf(wgt[k], ms[k][i], g);
        const float s2  = 1.0f / (1.0f + expf(-lamda2[i]));
        const float lam = s1 * s2;
        orow[i] = g * lam + xs[i] * (1.0f - lam);
    }
}

// ---------------------------------------------------------------------------
static float* symaddr(const void* sym)
{
    void* p = nullptr;
    cudaGetSymbolAddress(&p, sym);
    return (float*)p;
}

extern "C" void kernel_launch(void* const* d_in, const int* in_sizes, int n_in,
                              void* d_out, int out_size)
{
    const float* x_loc   = (const float*)d_in[0];
    const float* map_raw = (const float*)d_in[1];
    const float* cp_w1   = (const float*)d_in[2];
    const float* cp_b1   = (const float*)d_in[3];
    const float* cp_w2   = (const float*)d_in[4];
    const float* cp_b2   = (const float*)d_in[5];
    const float* de_w1   = (const float*)d_in[6];
    const float* de_b1   = (const float*)d_in[7];
    const float* de_w2   = (const float*)d_in[8];
    const float* de_b2   = (const float*)d_in[9];
    const float* lamda1  = (const float*)d_in[10];
    const float* lamda2  = (const float*)d_in[11];
    const int*   indices = (const int*)d_in[12];
    float* out = (float*)d_out;

    float* h1    = symaddr(g_h1);
    float* mapT  = symaddr(g_mapT);
    float* h2    = symaddr(g_h2);
    float* mapst = symaddr(g_mapst);

    const int M1 = CHN * LSEQ;   // 32768
    const int M3 = CHN * DCP;    // 16384

    // GEMM1: (32768,128)@(128,256) + b, relu -> h1
    gemm_tc<true,  false><<<dim3(DCP / BN, M1 / BM), 256>>>(map_raw, cp_w1, cp_b1, h1, M1, DCP, INTER);
    // GEMM2: (32768,256)@(256,256) + b -> mapT (transposed store to (C,Dcp,L))
    gemm_tc<false, true ><<<dim3(DCP / BN, M1 / BM), 256>>>(h1, cp_w2, cp_b2, mapT, M1, DCP, DCP);
    // GEMM3: (16384,512)@(512,1024) + b, relu -> h2
    gemm_tc<true,  false><<<dim3(DDE / BN, M3 / BM), 256>>>(mapT, de_w1, de_b1, h2, M3, DDE, LSEQ);
    // GEMM4: (16384,1024)@(1024,512) + b -> mapst
    gemm_tc<false, false><<<dim3(LSEQ / BN, M3 / BM), 256>>>(h2, de_w2, de_b2, mapst, M3, LSEQ, DDE);
    // Fused gather/score/softmax/blend
    fuse_k<<<BATCH * CHN, 256>>>(x_loc, mapst, indices, lamda1, lamda2, out);
}

// round 3
// speedup vs baseline: 3.9444x; 1.4624x over previous
#include <cuda_runtime.h>
#include <cstdint>

// Problem constants
#define BATCH 64
#define CHN   64
#define LSEQ  512
#define INTER 128
#define DCP   256
#define DDE   1024
#define KSEL  16
#define SCALE 0.05f

// Scratch (device globals; no runtime allocation)
__device__ float g_h1[(size_t)CHN * LSEQ * DCP];      // (C*L, 256)  after GEMM1+relu
__device__ float g_mapT[(size_t)CHN * DCP * LSEQ];    // (C, 256, 512) after GEMM2 (transposed store)
__device__ float g_h2[(size_t)CHN * DCP * DDE];       // (C*256, 1024) after GEMM3+relu
__device__ float g_mapst[(size_t)CHN * DCP * LSEQ];   // (C*256, 512) after GEMM4

// ---------------------------------------------------------------------------
// BF16 tensor-core GEMM: C = act(A(MxK) @ B(KxN) + bias(N))
// BM=BN=128, BK=32, 256 threads = 8 warps in 4(M) x 2(N); warp tile 32x64.
// mma.sync.aligned.m16n8k16.row.col.f32.bf16.bf16.f32
// Smem stores bf16 K-PAIRS packed in uint32: As[k2][m] holds {bf16(k=2*k2), bf16(2*k2+1)}.
// Fragment index arithmetic identical to tf32 m16n8k8 with k2 in place of k.
// +8 pad -> fragment LDS conflict-free (bank = 8*k2 + col mod 32 spans all banks).
// ---------------------------------------------------------------------------
#define BM 128
#define BN 128
#define BK 32
#define BK2 (BK / 2)

__device__ __forceinline__ uint32_t packbf(float lo, float hi) {
    uint32_t r;
    asm("cvt.rn.bf16x2.f32 %0, %1, %2;" : "=r"(r) : "f"(hi), "f"(lo));
    return r;
}

template<bool RELU, bool SWAP>
__global__ __launch_bounds__(256) void gemm_tc(const float* __restrict__ A,
                                               const float* __restrict__ B,
                                               const float* __restrict__ bias,
                                               float* __restrict__ C,
                                               int M, int N, int K)
{
    __shared__ uint32_t As[BK2][BM + 8];   // [k2][m]
    __shared__ uint32_t Bs[BK2][BN + 8];   // [k2][n]

    const int t    = threadIdx.x;
    const int lane = t & 31;
    const int w    = t >> 5;
    const int wm   = (w & 3) * 32;        // warp m offset in tile
    const int wn   = (w >> 2) * 64;       // warp n offset in tile
    const int bm   = blockIdx.y * BM;
    const int bn   = blockIdx.x * BN;

    // staging assignments
    const int am  = t >> 2;               // 0..63 (A rows am, am+64)
    const int ak  = (t & 3) * 8;          // 0,8,16,24 (8 consecutive k)
    const int bkr = t >> 5;               // 0..7 -> k2 rows bkr, bkr+8
    const int bn4 = (t & 31) * 4;         // 0..124

    const float* Ag = A + (size_t)(bm + am) * K + ak;
    const float* Bg = B + (size_t)(2 * bkr) * N + bn + bn4;

    float4 ra0 = *(const float4*)(Ag);
    float4 ra1 = *(const float4*)(Ag + 4);
    float4 ra2 = *(const float4*)(Ag + (size_t)64 * K);
    float4 ra3 = *(const float4*)(Ag + (size_t)64 * K + 4);
    float4 rb0 = *(const float4*)(Bg);
    float4 rb1 = *(const float4*)(Bg + (size_t)N);
    float4 rb2 = *(const float4*)(Bg + (size_t)16 * N);
    float4 rb3 = *(const float4*)(Bg + (size_t)17 * N);

    float acc[2][8][4];
    #pragma unroll
    for (int i = 0; i < 2; i++)
        #pragma unroll
        for (int j = 0; j < 8; j++)
            #pragma unroll
            for (int q = 0; q < 4; q++) acc[i][j][q] = 0.0f;

    const int ak2 = ak >> 1;             // k2 base for A staging
    const int ntiles = K / BK;
    for (int kt = 0; kt < ntiles; kt++) {
        // stage regs -> smem as packed bf16 pairs
        As[ak2 + 0][am]      = packbf(ra0.x, ra0.y);
        As[ak2 + 1][am]      = packbf(ra0.z, ra0.w);
        As[ak2 + 2][am]      = packbf(ra1.x, ra1.y);
        As[ak2 + 3][am]      = packbf(ra1.z, ra1.w);
        As[ak2 + 0][am + 64] = packbf(ra2.x, ra2.y);
        As[ak2 + 1][am + 64] = packbf(ra2.z, ra2.w);
        As[ak2 + 2][am + 64] = packbf(ra3.x, ra3.y);
        As[ak2 + 3][am + 64] = packbf(ra3.z, ra3.w);
        {
            uint4 v0 = make_uint4(packbf(rb0.x, rb1.x), packbf(rb0.y, rb1.y),
                                  packbf(rb0.z, rb1.z), packbf(rb0.w, rb1.w));
            uint4 v1 = make_uint4(packbf(rb2.x, rb3.x), packbf(rb2.y, rb3.y),
                                  packbf(rb2.z, rb3.z), packbf(rb2.w, rb3.w));
            *(uint4*)&Bs[bkr][bn4]     = v0;
            *(uint4*)&Bs[bkr + 8][bn4] = v1;
        }
        __syncthreads();

        // prefetch next tile
        if (kt + 1 < ntiles) {
            const float* Agn = Ag + (kt + 1) * BK;
            const float* Bgn = Bg + (size_t)(kt + 1) * BK * N;
            ra0 = *(const float4*)(Agn);
            ra1 = *(const float4*)(Agn + 4);
            ra2 = *(const float4*)(Agn + (size_t)64 * K);
            ra3 = *(const float4*)(Agn + (size_t)64 * K + 4);
            rb0 = *(const float4*)(Bgn);
            rb1 = *(const float4*)(Bgn + (size_t)N);
            rb2 = *(const float4*)(Bgn + (size_t)16 * N);
            rb3 = *(const float4*)(Bgn + (size_t)17 * N);
        }

        // compute: 2 k16-steps
        #pragma unroll
        for (int ks = 0; ks < 2; ks++) {
            const int kb = ks * 8;                       // k2 base of this k16 step
            uint32_t af[2][4];
            #pragma unroll
            for (int mi = 0; mi < 2; mi++) {
                const int r0 = wm + mi * 16 + (lane >> 2);
                const int c0 = kb + (lane & 3);
                af[mi][0] = As[c0][r0];
                af[mi][1] = As[c0][r0 + 8];
                af[mi][2] = As[c0 + 4][r0];
                af[mi][3] = As[c0 + 4][r0 + 8];
            }
            #pragma unroll
            for (int ni = 0; ni < 8; ni++) {
                const int nn = wn + ni * 8 + (lane >> 2);
                const uint32_t b0 = Bs[kb + (lane & 3)][nn];
                const uint32_t b1 = Bs[kb + (lane & 3) + 4][nn];
                #pragma unroll
                for (int mi = 0; mi < 2; mi++) {
                    asm volatile(
                        "mma.sync.aligned.m16n8k16.row.col.f32.bf16.bf16.f32 "
                        "{%0,%1,%2,%3}, {%4,%5,%6,%7}, {%8,%9}, {%0,%1,%2,%3};"
                        : "+f"(acc[mi][ni][0]), "+f"(acc[mi][ni][1]),
                          "+f"(acc[mi][ni][2]), "+f"(acc[mi][ni][3])
                        : "r"(af[mi][0]), "r"(af[mi][1]), "r"(af[mi][2]), "r"(af[mi][3]),
                          "r"(b0), "r"(b1));
                }
            }
        }
        __syncthreads();
    }

    // epilogue: c0,c1 -> (row, col), (row, col+1); c2,c3 -> (row+8, ...)
    #pragma unroll
    for (int mi = 0; mi < 2; mi++) {
        const int r = bm + wm + mi * 16 + (lane >> 2);
        #pragma unroll
        for (int ni = 0; ni < 8; ni++) {
            const int col = bn + wn + ni * 8 + 2 * (lane & 3);
            const float bv0 = bias[col];
            const float bv1 = bias[col + 1];
            #pragma unroll
            for (int h = 0; h < 2; h++) {
                const int m = r + h * 8;
                float v0 = acc[mi][ni][h * 2 + 0] + bv0;
                float v1 = acc[mi][ni][h * 2 + 1] + bv1;
                if (RELU) { v0 = fmaxf(v0, 0.0f); v1 = fmaxf(v1, 0.0f); }
                if (SWAP) {
                    const int c = m >> 9;      // m / 512
                    const int l = m & 511;     // m % 512
                    C[((size_t)c * DCP + col) * LSEQ + l]     = v0;
                    C[((size_t)c * DCP + col + 1) * LSEQ + l] = v1;
                } else {
                    *(float2*)&C[(size_t)m * N + col] = make_float2(v0, v1);
                }
            }
        }
    }
}

// ---------------------------------------------------------------------------
// Fused tail: gather K rows, L1 scores, softmax, weighted sum, gated blend.
// One block per (b, c). 256 threads.
// ---------------------------------------------------------------------------
__global__ __launch_bounds__(256) void fuse_k(const float* __restrict__ x_loc,
                                              const float* __restrict__ map_st,
                                              const int*   __restrict__ indices,
                                              const float* __restrict__ lamda1,
                                              const float* __restrict__ lamda2,
                                              float* __restrict__ out)
{
    __shared__ float xs[LSEQ];
    __shared__ float ms[KSEL][LSEQ];
    __shared__ float warpsum[KSEL][8];
    __shared__ float wgt[KSEL];

    const int bc = blockIdx.x;        // b*CHN + c
    const int c  = bc & (CHN - 1);
    const int t  = threadIdx.x;

    const float* xrow = x_loc + (size_t)bc * LSEQ;
    for (int i = t; i < LSEQ; i += 256) xs[i] = xrow[i];

    #pragma unroll
    for (int k = 0; k < KSEL; k++) {
        const int d = indices[bc * KSEL + k];
        const float* mrow = map_st + ((size_t)c * DCP + d) * LSEQ;
        for (int i = t; i < LSEQ; i += 256) ms[k][i] = mrow[i];
    }
    __syncthreads();

    float part[KSEL];
    #pragma unroll
    for (int k = 0; k < KSEL; k++) part[k] = 0.0f;
    for (int i = t; i < LSEQ; i += 256) {
        const float x = xs[i];
        #pragma unroll
        for (int k = 0; k < KSEL; k++) part[k] += fabsf(x - ms[k][i]);
    }

    const int lane = t & 31, w = t >> 5;
    #pragma unroll
    for (int k = 0; k < KSEL; k++) {
        float v = part[k];
        #pragma unroll
        for (int off = 16; off > 0; off >>= 1)
            v += __shfl_down_sync(0xffffffffu, v, off);
        if (lane == 0) warpsum[k][w] = v;
    }
    __syncthreads();

    if (t < KSEL) {
        float s = 0.0f;
        #pragma unroll
        for (int ww = 0; ww < 8; ww++) s += warpsum[t][ww];
        float score = -s * SCALE;
        float mx = score;
        #pragma unroll
        for (int off = 8; off > 0; off >>= 1)
            mx = fmaxf(mx, __shfl_xor_sync(0x0000ffffu, mx, off));
        float e  = expf(score - mx);
        float se = e;
        #pragma unroll
        for (int off = 8; off > 0; off >>= 1)
            se += __shfl_xor_sync(0x0000ffffu, se, off);
        wgt[t] = e / se;
    }
    __syncthreads();

    const float s1 = 1.0f / (1.0f + expf(-lamda1[c]));
    float* orow = out + (size_t)bc * LSEQ;
    for (int i = t; i < LSEQ; i += 256) {
        float g = 0.0f;
        #pragma unroll
        for (int k = 0; k < KSEL; k++) g = fmaf(wgt[k], ms[k][i], g);
        const float s2  = 1.0f / (1.0f + expf(-lamda2[i]));
        const float lam = s1 * s2;
        orow[i] = g * lam + xs[i] * (1.0f - lam);
    }
}

// ---------------------------------------------------------------------------
static float* symaddr(const void* sym)
{
    void* p = nullptr;
    cudaGetSymbolAddress(&p, sym);
    return (float*)p;
}

extern "C" void kernel_launch(void* const* d_in, const int* in_sizes, int n_in,
                              void* d_out, int out_size)
{
    const float* x_loc   = (const float*)d_in[0];
    const float* map_raw = (const float*)d_in[1];
    const float* cp_w1   = (const float*)d_in[2];
    const float* cp_b1   = (const float*)d_in[3];
    const float* cp_w2   = (const float*)d_in[4];
    const float* cp_b2   = (const float*)d_in[5];
    const float* de_w1   = (const float*)d_in[6];
    const float* de_b1   = (const float*)d_in[7];
    const float* de_w2   = (const float*)d_in[8];
    const float* de_b2   = (const float*)d_in[9];
    const float* lamda1  = (const float*)d_in[10];
    const float* lamda2  = (const float*)d_in[11];
    const int*   indices = (const int*)d_in[12];
    float* out = (float*)d_out;

    float* h1    = symaddr(g_h1);
    float* mapT  = symaddr(g_mapT);
    float* h2    = symaddr(g_h2);
    float* mapst = symaddr(g_mapst);

    const int M1 = CHN * LSEQ;   // 32768
    const int M3 = CHN * DCP;    // 16384

    // GEMM1: (32768,128)@(128,256) + b, relu -> h1
    gemm_tc<true,  false><<<dim3(DCP / BN, M1 / BM), 256>>>(map_raw, cp_w1, cp_b1, h1, M1, DCP, INTER);
    // GEMM2: (32768,256)@(256,256) + b -> mapT (transposed store to (C,Dcp,L))
    gemm_tc<false, true ><<<dim3(DCP / BN, M1 / BM), 256>>>(h1, cp_w2, cp_b2, mapT, M1, DCP, DCP);
    // GEMM3: (16384,512)@(512,1024) + b, relu -> h2
    gemm_tc<true,  false><<<dim3(DDE / BN, M3 / BM), 256>>>(mapT, de_w1, de_b1, h2, M3, DDE, LSEQ);
    // GEMM4: (16384,1024)@(1024,512) + b -> mapst
    gemm_tc<false, false><<<dim3(LSEQ / BN, M3 / BM), 256>>>(h2, de_w2, de_b2, mapst, M3, LSEQ, DDE);
    // Fused gather/score/softmax/blend
    fuse_k<<<BATCH * CHN, 256>>>(x_loc, mapst, indices, lamda1, lamda2, out);
}

// round 4
// speedup vs baseline: 4.2751x; 1.0838x over previous
#include <cuda_runtime.h>
#include <cuda_bf16.h>
#include <cstdint>

// Problem constants
#define BATCH 64
#define CHN   64
#define LSEQ  512
#define INTER 128
#define DCP   256
#define DDE   1024
#define KSEL  16
#define SCALE 0.05f

// Scratch (device globals; no runtime allocation)
__device__ __align__(16) __nv_bfloat16 g_mapraw[(size_t)CHN * LSEQ * INTER];
__device__ __align__(16) __nv_bfloat16 g_wcp1[INTER * DCP];
__device__ __align__(16) __nv_bfloat16 g_wcp2[DCP * DCP];
__device__ __align__(16) __nv_bfloat16 g_wde1[LSEQ * DDE];
__device__ __align__(16) __nv_bfloat16 g_wde2[DDE * LSEQ];
__device__ __align__(16) __nv_bfloat16 g_h1b[(size_t)CHN * LSEQ * DCP];
__device__ __align__(16) __nv_bfloat16 g_mapTb[(size_t)CHN * DCP * LSEQ];
__device__ __align__(16) __nv_bfloat16 g_h2b[(size_t)CHN * DCP * DDE];
__device__ float g_mapst[(size_t)CHN * DCP * LSEQ];

__device__ __forceinline__ uint32_t packbf(float lo, float hi) {
    uint32_t r;
    asm("cvt.rn.bf16x2.f32 %0, %1, %2;" : "=r"(r) : "f"(hi), "f"(lo));
    return r;
}
__device__ __forceinline__ uint32_t prmt(uint32_t a, uint32_t b, uint32_t s) {
    uint32_t d;
    asm("prmt.b32 %0, %1, %2, %3;" : "=r"(d) : "r"(a), "r"(b), "r"(s));
    return d;
}

// ---------------------------------------------------------------------------
// f32 -> bf16 convert (n multiple of 4)
// ---------------------------------------------------------------------------
__global__ void cvt_bf(const float* __restrict__ src, __nv_bfloat16* __restrict__ dst, int n)
{
    const int i = (blockIdx.x * blockDim.x + threadIdx.x) * 4;
    if (i < n) {
        float4 v = *(const float4*)(src + i);
        uint2 o;
        o.x = packbf(v.x, v.y);
        o.y = packbf(v.z, v.w);
        *(uint2*)(dst + i) = o;
    }
}

// ---------------------------------------------------------------------------
// BF16 tensor-core GEMM: C = act(A(MxK)bf16 @ B(KxN)bf16 + bias(N)f32)
// BM=BN=128, BK=32, 256 threads, 8 warps 4(M)x2(N), warp tile 32x64.
// Double-buffered smem, one __syncthreads per k-iteration.
// Smem layout: As[buf][k2][m], Bs[buf][k2][n] as packed bf16 k-pairs (uint32).
// OUTBF: store output as bf16 (intermediates); else f32.
// SWAP: scatter-store out[m,n] -> g[(m/512)*256*512 + n*512 + (m%512)].
// ---------------------------------------------------------------------------
#define BM 128
#define BN 128
#define BK 32
#define BK2 (BK / 2)

template<bool RELU, bool SWAP, bool OUTBF>
__global__ __launch_bounds__(256) void gemm_bf(const __nv_bfloat16* __restrict__ A,
                                               const __nv_bfloat16* __restrict__ B,
                                               const float* __restrict__ bias,
                                               void* __restrict__ Cout,
                                               int M, int N, int K)
{
    __shared__ uint32_t As[2][BK2][BM + 8];
    __shared__ uint32_t Bs[2][BK2][BN + 8];

    const int t    = threadIdx.x;
    const int lane = t & 31;
    const int w    = t >> 5;
    const int wm   = (w & 3) * 32;
    const int wn   = (w >> 2) * 64;
    const int bm   = blockIdx.y * BM;
    const int bn   = blockIdx.x * BN;

    // A staging: thread covers row arow, k-half ahalf (16 bf16 = 8 pairs)
    const int arow  = t >> 1;             // 0..127
    const int ahalf = t & 1;              // k element base = ahalf*16
    const int ak2   = ahalf * 8;
    const __nv_bfloat16* Ag = A + (size_t)(bm + arow) * K + ahalf * 16;

    // B staging: thread covers k2 row bk2 (global rows 2*bk2, 2*bk2+1), 8 n
    const int bk2 = t >> 4;               // 0..15
    const int bn8 = (t & 15) * 8;
    const __nv_bfloat16* Bg = B + (size_t)(2 * bk2) * N + bn + bn8;

    uint4 va0, va1, vb0, vb1;

#define LOADTILE(kt)                                                              \
    do {                                                                          \
        const __nv_bfloat16* ap = Ag + (kt) * BK;                                 \
        const __nv_bfloat16* bp = Bg + (size_t)(kt) * BK * N;                     \
        va0 = *(const uint4*)(ap);                                                \
        va1 = *(const uint4*)(ap + 8);                                            \
        vb0 = *(const uint4*)(bp);                                                \
        vb1 = *(const uint4*)(bp + (size_t)N);                                    \
    } while (0)

#define STORETILE(buf)                                                            \
    do {                                                                          \
        As[buf][ak2 + 0][arow] = va0.x;                                           \
        As[buf][ak2 + 1][arow] = va0.y;                                           \
        As[buf][ak2 + 2][arow] = va0.z;                                           \
        As[buf][ak2 + 3][arow] = va0.w;                                           \
        As[buf][ak2 + 4][arow] = va1.x;                                           \
        As[buf][ak2 + 5][arow] = va1.y;                                           \
        As[buf][ak2 + 6][arow] = va1.z;                                           \
        As[buf][ak2 + 7][arow] = va1.w;                                           \
        uint4 o0, o1;                                                             \
        o0.x = prmt(vb0.x, vb1.x, 0x5410u); o0.y = prmt(vb0.x, vb1.x, 0x7632u);   \
        o0.z = prmt(vb0.y, vb1.y, 0x5410u); o0.w = prmt(vb0.y, vb1.y, 0x7632u);   \
        o1.x = prmt(vb0.z, vb1.z, 0x5410u); o1.y = prmt(vb0.z, vb1.z, 0x7632u);   \
        o1.z = prmt(vb0.w, vb1.w, 0x5410u); o1.w = prmt(vb0.w, vb1.w, 0x7632u);   \
        *(uint4*)&Bs[buf][bk2][bn8]     = o0;                                     \
        *(uint4*)&Bs[buf][bk2][bn8 + 4] = o1;                                     \
    } while (0)

    float acc[2][8][4];
    #pragma unroll
    for (int i = 0; i < 2; i++)
        #pragma unroll
        for (int j = 0; j < 8; j++)
            #pragma unroll
            for (int q = 0; q < 4; q++) acc[i][j][q] = 0.0f;

    const int ntiles = K / BK;

    LOADTILE(0);
    STORETILE(0);
    __syncthreads();

    for (int kt = 0; kt < ntiles; kt++) {
        const int cur = kt & 1;
        if (kt + 1 < ntiles) LOADTILE(kt + 1);

        #pragma unroll
        for (int ks = 0; ks < 2; ks++) {
            const int kb = ks * 8;
            uint32_t af[2][4];
            #pragma unroll
            for (int mi = 0; mi < 2; mi++) {
                const int r0 = wm + mi * 16 + (lane >> 2);
                const int c0 = kb + (lane & 3);
                af[mi][0] = As[cur][c0][r0];
                af[mi][1] = As[cur][c0][r0 + 8];
                af[mi][2] = As[cur][c0 + 4][r0];
                af[mi][3] = As[cur][c0 + 4][r0 + 8];
            }
            #pragma unroll
            for (int ni = 0; ni < 8; ni++) {
                const int nn = wn + ni * 8 + (lane >> 2);
                const uint32_t b0 = Bs[cur][kb + (lane & 3)][nn];
                const uint32_t b1 = Bs[cur][kb + (lane & 3) + 4][nn];
                #pragma unroll
                for (int mi = 0; mi < 2; mi++) {
                    asm volatile(
                        "mma.sync.aligned.m16n8k16.row.col.f32.bf16.bf16.f32 "
                        "{%0,%1,%2,%3}, {%4,%5,%6,%7}, {%8,%9}, {%0,%1,%2,%3};"
                        : "+f"(acc[mi][ni][0]), "+f"(acc[mi][ni][1]),
                          "+f"(acc[mi][ni][2]), "+f"(acc[mi][ni][3])
                        : "r"(af[mi][0]), "r"(af[mi][1]), "r"(af[mi][2]), "r"(af[mi][3]),
                          "r"(b0), "r"(b1));
                }
            }
        }

        if (kt + 1 < ntiles) {
            STORETILE((kt + 1) & 1);
            __syncthreads();
        }
    }

    // epilogue
    #pragma unroll
    for (int mi = 0; mi < 2; mi++) {
        const int r = bm + wm + mi * 16 + (lane >> 2);
        #pragma unroll
        for (int ni = 0; ni < 8; ni++) {
            const int col = bn + wn + ni * 8 + 2 * (lane & 3);
            const float bv0 = bias[col];
            const float bv1 = bias[col + 1];
            #pragma unroll
            for (int h = 0; h < 2; h++) {
                const int m = r + h * 8;
                float v0 = acc[mi][ni][h * 2 + 0] + bv0;
                float v1 = acc[mi][ni][h * 2 + 1] + bv1;
                if (RELU) { v0 = fmaxf(v0, 0.0f); v1 = fmaxf(v1, 0.0f); }
                if (SWAP) {
                    const int c = m >> 9;
                    const int l = m & 511;
                    if (OUTBF) {
                        __nv_bfloat16* Cb = (__nv_bfloat16*)Cout;
                        Cb[((size_t)c * DCP + col) * LSEQ + l]     = __float2bfloat16(v0);
                        Cb[((size_t)c * DCP + col + 1) * LSEQ + l] = __float2bfloat16(v1);
                    } else {
                        float* Cf = (float*)Cout;
                        Cf[((size_t)c * DCP + col) * LSEQ + l]     = v0;
                        Cf[((size_t)c * DCP + col + 1) * LSEQ + l] = v1;
                    }
                } else {
                    if (OUTBF) {
                        *(uint32_t*)((__nv_bfloat16*)Cout + (size_t)m * N + col) = packbf(v0, v1);
                    } else {
                        *(float2*)((float*)Cout + (size_t)m * N + col) = make_float2(v0, v1);
                    }
                }
            }
        }
    }
#undef LOADTILE
#undef STORETILE
}

// ---------------------------------------------------------------------------
// Fused tail: gather K rows, L1 scores, softmax, weighted sum, gated blend.
// ---------------------------------------------------------------------------
__global__ __launch_bounds__(256) void fuse_k(const float* __restrict__ x_loc,
                                              const float* __restrict__ map_st,
                                              const int*   __restrict__ indices,
                                              const float* __restrict__ lamda1,
                                              const float* __restrict__ lamda2,
                                              float* __restrict__ out)
{
    __shared__ float xs[LSEQ];
    __shared__ float ms[KSEL][LSEQ];
    __shared__ float warpsum[KSEL][8];
    __shared__ float wgt[KSEL];

    const int bc = blockIdx.x;
    const int c  = bc & (CHN - 1);
    const int t  = threadIdx.x;

    const float* xrow = x_loc + (size_t)bc * LSEQ;
    for (int i = t; i < LSEQ; i += 256) xs[i] = xrow[i];

    #pragma unroll
    for (int k = 0; k < KSEL; k++) {
        const int d = indices[bc * KSEL + k];
        const float* mrow = map_st + ((size_t)c * DCP + d) * LSEQ;
        for (int i = t; i < LSEQ; i += 256) ms[k][i] = mrow[i];
    }
    __syncthreads();

    float part[KSEL];
    #pragma unroll
    for (int k = 0; k < KSEL; k++) part[k] = 0.0f;
    for (int i = t; i < LSEQ; i += 256) {
        const float x = xs[i];
        #pragma unroll
        for (int k = 0; k < KSEL; k++) part[k] += fabsf(x - ms[k][i]);
    }

    const int lane = t & 31, w = t >> 5;
    #pragma unroll
    for (int k = 0; k < KSEL; k++) {
        float v = part[k];
        #pragma unroll
        for (int off = 16; off > 0; off >>= 1)
            v += __shfl_down_sync(0xffffffffu, v, off);
        if (lane == 0) warpsum[k][w] = v;
    }
    __syncthreads();

    if (t < KSEL) {
        float s = 0.0f;
        #pragma unroll
        for (int ww = 0; ww < 8; ww++) s += warpsum[t][ww];
        float score = -s * SCALE;
        float mx = score;
        #pragma unroll
        for (int off = 8; off > 0; off >>= 1)
            mx = fmaxf(mx, __shfl_xor_sync(0x0000ffffu, mx, off));
        float e  = expf(score - mx);
        float se = e;
        #pragma unroll
        for (int off = 8; off > 0; off >>= 1)
            se += __shfl_xor_sync(0x0000ffffu, se, off);
        wgt[t] = e / se;
    }
    __syncthreads();

    const float s1 = 1.0f / (1.0f + expf(-lamda1[c]));
    float* orow = out + (size_t)bc * LSEQ;
    for (int i = t; i < LSEQ; i += 256) {
        float g = 0.0f;
        #pragma unroll
        for (int k = 0; k < KSEL; k++) g = fmaf(wgt[k], ms[k][i], g);
        const float s2  = 1.0f / (1.0f + expf(-lamda2[i]));
        const float lam = s1 * s2;
        orow[i] = g * lam + xs[i] * (1.0f - lam);
    }
}

// ---------------------------------------------------------------------------
static void* symaddr(const void* sym)
{
    void* p = nullptr;
    cudaGetSymbolAddress(&p, sym);
    return p;
}

extern "C" void kernel_launch(void* const* d_in, const int* in_sizes, int n_in,
                              void* d_out, int out_size)
{
    const float* x_loc   = (const float*)d_in[0];
    const float* map_raw = (const float*)d_in[1];
    const float* cp_w1   = (const float*)d_in[2];
    const float* cp_b1   = (const float*)d_in[3];
    const float* cp_w2   = (const float*)d_in[4];
    const float* cp_b2   = (const float*)d_in[5];
    const float* de_w1   = (const float*)d_in[6];
    const float* de_b1   = (const float*)d_in[7];
    const float* de_w2   = (const float*)d_in[8];
    const float* de_b2   = (const float*)d_in[9];
    const float* lamda1  = (const float*)d_in[10];
    const float* lamda2  = (const float*)d_in[11];
    const int*   indices = (const int*)d_in[12];
    float* out = (float*)d_out;

    __nv_bfloat16* mapraw = (__nv_bfloat16*)symaddr(g_mapraw);
    __nv_bfloat16* wcp1   = (__nv_bfloat16*)symaddr(g_wcp1);
    __nv_bfloat16* wcp2   = (__nv_bfloat16*)symaddr(g_wcp2);
    __nv_bfloat16* wde1   = (__nv_bfloat16*)symaddr(g_wde1);
    __nv_bfloat16* wde2   = (__nv_bfloat16*)symaddr(g_wde2);
    __nv_bfloat16* h1b    = (__nv_bfloat16*)symaddr(g_h1b);
    __nv_bfloat16* mapTb  = (__nv_bfloat16*)symaddr(g_mapTb);
    __nv_bfloat16* h2b    = (__nv_bfloat16*)symaddr(g_h2b);
    float*         mapst  = (float*)symaddr(g_mapst);

    const int M1 = CHN * LSEQ;   // 32768
    const int M3 = CHN * DCP;    // 16384

    // Convert inputs to bf16
    auto cv = [](const float* s, __nv_bfloat16* d, int n) {
        cvt_bf<<<(n / 4 + 255) / 256, 256>>>(s, d, n);
    };
    cv(map_raw, mapraw, M1 * INTER);
    cv(cp_w1, wcp1, INTER * DCP);
    cv(cp_w2, wcp2, DCP * DCP);
    cv(de_w1, wde1, LSEQ * DDE);
    cv(de_w2, wde2, DDE * LSEQ);

    // GEMM1: (32768,128)@(128,256) + b, relu -> h1 (bf16)
    gemm_bf<true,  false, true ><<<dim3(DCP / BN, M1 / BM), 256>>>(mapraw, wcp1, cp_b1, h1b, M1, DCP, INTER);
    // GEMM2: (32768,256)@(256,256) + b -> mapT (bf16, transposed store)
    gemm_bf<false, true,  true ><<<dim3(DCP / BN, M1 / BM), 256>>>(h1b, wcp2, cp_b2, mapTb, M1, DCP, DCP);
    // GEMM3: (16384,512)@(512,1024) + b, relu -> h2 (bf16)
    gemm_bf<true,  false, true ><<<dim3(DDE / BN, M3 / BM), 256>>>(mapTb, wde1, de_b1, h2b, M3, DDE, LSEQ);
    // GEMM4: (16384,1024)@(1024,512) + b -> mapst (f32)
    gemm_bf<false, false, false><<<dim3(LSEQ / BN, M3 / BM), 256>>>(h2b, wde2, de_b2, mapst, M3, LSEQ, DDE);
    // Fused gather/score/softmax/blend
    fuse_k<<<BATCH * CHN, 256>>>(x_loc, mapst, indices, lamda1, lamda2, out);
}

// round 5
// speedup vs baseline: 5.7900x; 1.3544x over previous
#include <cuda_runtime.h>
#include <cuda_bf16.h>
#include <cstdint>

// Problem constants
#define BATCH 64
#define CHN   64
#define LSEQ  512
#define INTER 128
#define DCP   256
#define DDE   1024
#define KSEL  16
#define SCALE 0.05f

// Scratch (device globals; no runtime allocation)
__device__ __align__(16) __nv_bfloat16 g_mapraw[(size_t)CHN * LSEQ * INTER];
__device__ __align__(16) __nv_bfloat16 g_wcp1[INTER * DCP];
__device__ __align__(16) __nv_bfloat16 g_wcp2[DCP * DCP];
__device__ __align__(16) __nv_bfloat16 g_wde1[LSEQ * DDE];
__device__ __align__(16) __nv_bfloat16 g_wde2[DDE * LSEQ];
__device__ __align__(16) __nv_bfloat16 g_h1b[(size_t)CHN * LSEQ * DCP];
__device__ __align__(16) __nv_bfloat16 g_mapTb[(size_t)CHN * DCP * LSEQ];
__device__ __align__(16) __nv_bfloat16 g_h2b[(size_t)CHN * DCP * DDE];
__device__ float g_mapst[(size_t)CHN * DCP * LSEQ];

__device__ __forceinline__ uint32_t packbf(float lo, float hi) {
    uint32_t r;
    asm("cvt.rn.bf16x2.f32 %0, %1, %2;" : "=r"(r) : "f"(hi), "f"(lo));
    return r;
}

// ---------------------------------------------------------------------------
// Single merged f32->bf16 convert over all 5 tensors.
// ---------------------------------------------------------------------------
#define N_MAPRAW (CHN * LSEQ * INTER)     // 4194304
#define N_WCP1   (INTER * DCP)            // 32768
#define N_WCP2   (DCP * DCP)              // 65536
#define N_WDE1   (LSEQ * DDE)             // 524288
#define N_WDE2   (DDE * LSEQ)             // 524288
#define N_CVT_TOT (N_MAPRAW + N_WCP1 + N_WCP2 + N_WDE1 + N_WDE2)

__global__ void cvt_all(const float* __restrict__ s0, __nv_bfloat16* __restrict__ d0,
                        const float* __restrict__ s1, __nv_bfloat16* __restrict__ d1,
                        const float* __restrict__ s2, __nv_bfloat16* __restrict__ d2,
                        const float* __restrict__ s3, __nv_bfloat16* __restrict__ d3,
                        const float* __restrict__ s4, __nv_bfloat16* __restrict__ d4)
{
    int i = (blockIdx.x * blockDim.x + threadIdx.x) * 4;
    const float* s;
    __nv_bfloat16* d;
    if (i < N_MAPRAW)                          { s = s0; d = d0; }
    else if ((i -= N_MAPRAW) < N_WCP1)         { s = s1; d = d1; }
    else if ((i -= N_WCP1) < N_WCP2)           { s = s2; d = d2; }
    else if ((i -= N_WCP2) < N_WDE1)           { s = s3; d = d3; }
    else          { i -= N_WDE1;                 s = s4; d = d4; }
    float4 v = *(const float4*)(s + i);
    uint2 o;
    o.x = packbf(v.x, v.y);
    o.y = packbf(v.z, v.w);
    *(uint2*)(d + i) = o;
}

// ---------------------------------------------------------------------------
// BF16 tensor-core GEMM, cp.async 3-stage pipeline + ldmatrix.
// BM=BN=128, BK=32, 256 threads, 8 warps 4(M)x2(N), warp tile 32x64.
// Smem A: [stage][m][k] row-major, 64B rows, chunk swizzle c ^= (m>>1)&3.
// Smem B: [stage][k][n] row-major, 256B rows, chunk swizzle low3 ^= k&7.
// Fragments: A via ldmatrix.x4, B via ldmatrix.x4.trans.
// ---------------------------------------------------------------------------
#define BM 128
#define BN 128
#define BK 32
#define STAGES 3
#define ASTAGE 8192
#define BSTAGE 8192

__device__ __forceinline__ void cpasync16(uint32_t saddr, const void* gaddr) {
    asm volatile("cp.async.cg.shared.global [%0], [%1], 16;" :: "r"(saddr), "l"(gaddr));
}
__device__ __forceinline__ void ldsm4(uint32_t& r0, uint32_t& r1, uint32_t& r2, uint32_t& r3, uint32_t a) {
    asm volatile("ldmatrix.sync.aligned.m8n8.x4.shared.b16 {%0,%1,%2,%3}, [%4];"
                 : "=r"(r0), "=r"(r1), "=r"(r2), "=r"(r3) : "r"(a));
}
__device__ __forceinline__ void ldsm4t(uint32_t& r0, uint32_t& r1, uint32_t& r2, uint32_t& r3, uint32_t a) {
    asm volatile("ldmatrix.sync.aligned.m8n8.x4.trans.shared.b16 {%0,%1,%2,%3}, [%4];"
                 : "=r"(r0), "=r"(r1), "=r"(r2), "=r"(r3) : "r"(a));
}

template<bool RELU, bool SWAP, bool OUTBF>
__global__ __launch_bounds__(256, 2) void gemm_bf(const __nv_bfloat16* __restrict__ A,
                                                  const __nv_bfloat16* __restrict__ B,
                                                  const float* __restrict__ bias,
                                                  void* __restrict__ Cout,
                                                  int M, int N, int K)
{
    __shared__ __align__(16) char smem[STAGES * (ASTAGE + BSTAGE)];
    const uint32_t sA = (uint32_t)__cvta_generic_to_shared(smem);
    const uint32_t sB = sA + STAGES * ASTAGE;

    const int t    = threadIdx.x;
    const int lane = t & 31;
    const int w    = t >> 5;
    const int wm   = (w & 3) * 32;
    const int wn   = (w >> 2) * 64;
    const int bm   = blockIdx.y * BM;
    const int bn   = blockIdx.x * BN;

    // ---- cp.async per-thread assignments ----
    // A: thread covers rows m=t>>2 and m+64, k-chunk c=t&3 (8 bf16 = 16B)
    const int am = t >> 2;
    const int ac = t & 3;
    const __nv_bfloat16* gA = A + (size_t)(bm + am) * K + ac * 8;
    const uint32_t sAoff = (uint32_t)((am * 4 + (ac ^ ((am >> 1) & 3))) * 16);
    // (m+64)>>1 & 3 == (m>>1)&3, so second row is sAoff + 4096.

    // B: thread covers rows k=t>>4 and k+16, n-chunk c=t&15
    const int bk = t >> 4;
    const int bcc = t & 15;
    const __nv_bfloat16* gB = B + (size_t)bk * N + bn + bcc * 8;
    const uint32_t sBoff = (uint32_t)((bk * 16 + ((bcc & 8) | ((bcc & 7) ^ (bk & 7)))) * 16);
    // (k+16)&7 == k&7, so second row is sBoff + 4096.

    const int ntiles = K / BK;

#define ISSUE(kt)                                                                   \
    do {                                                                            \
        if ((kt) < ntiles) {                                                        \
            const uint32_t so = (uint32_t)(((kt) % STAGES));                        \
            const uint32_t sa = sA + so * ASTAGE + sAoff;                           \
            const uint32_t sb = sB + so * BSTAGE + sBoff;                           \
            const __nv_bfloat16* ga = gA + (kt) * BK;                               \
            const __nv_bfloat16* gb = gB + (size_t)(kt) * BK * N;                   \
            cpasync16(sa,        ga);                                               \
            cpasync16(sa + 4096, ga + (size_t)64 * K);                              \
            cpasync16(sb,        gb);                                               \
            cpasync16(sb + 4096, gb + (size_t)16 * N);                              \
        }                                                                           \
        asm volatile("cp.async.commit_group;");                                     \
    } while (0)

    float acc[2][8][4];
    #pragma unroll
    for (int i = 0; i < 2; i++)
        #pragma unroll
        for (int j = 0; j < 8; j++)
            #pragma unroll
            for (int q = 0; q < 4; q++) acc[i][j][q] = 0.0f;

    ISSUE(0);
    ISSUE(1);
    asm volatile("cp.async.wait_group 1;");
    __syncthreads();

    for (int kt = 0; kt < ntiles; kt++) {
        ISSUE(kt + 2);

        const uint32_t curA = sA + (uint32_t)(kt % STAGES) * ASTAGE;
        const uint32_t curB = sB + (uint32_t)(kt % STAGES) * BSTAGE;

        #pragma unroll
        for (int ks = 0; ks < 2; ks++) {
            // A fragments: 2 x ldsm.x4 (m16 x k16 each)
            uint32_t af[2][4];
            {
                const int cch = ks * 2 + (lane >> 4);          // 0..3
                #pragma unroll
                for (int mi = 0; mi < 2; mi++) {
                    const int m = wm + mi * 16 + (lane & 15);
                    const uint32_t a = curA + (uint32_t)((m * 4 + (cch ^ ((m >> 1) & 3))) * 16);
                    ldsm4(af[mi][0], af[mi][1], af[mi][2], af[mi][3], a);
                }
            }
            // B fragments: 4 x ldsm.x4.trans (k16 x n16 each)
            uint32_t bf[4][4];
            {
                const int k = ks * 16 + (lane & 7) + 8 * ((lane >> 3) & 1);
                const int nc0 = (wn >> 3) + (lane >> 4);
                #pragma unroll
                for (int j = 0; j < 4; j++) {
                    const int nc = nc0 + 2 * j;
                    const uint32_t swz = (uint32_t)((nc & 8) | ((nc & 7) ^ (k & 7)));
                    const uint32_t a = curB + (uint32_t)(k * 256) + swz * 16;
                    ldsm4t(bf[j][0], bf[j][1], bf[j][2], bf[j][3], a);
                }
            }
            #pragma unroll
            for (int ni = 0; ni < 8; ni++) {
                const uint32_t b0 = bf[ni >> 1][(ni & 1) * 2 + 0];
                const uint32_t b1 = bf[ni >> 1][(ni & 1) * 2 + 1];
                #pragma unroll
                for (int mi = 0; mi < 2; mi++) {
                    asm volatile(
                        "mma.sync.aligned.m16n8k16.row.col.f32.bf16.bf16.f32 "
                        "{%0,%1,%2,%3}, {%4,%5,%6,%7}, {%8,%9}, {%0,%1,%2,%3};"
                        : "+f"(acc[mi][ni][0]), "+f"(acc[mi][ni][1]),
                          "+f"(acc[mi][ni][2]), "+f"(acc[mi][ni][3])
                        : "r"(af[mi][0]), "r"(af[mi][1]), "r"(af[mi][2]), "r"(af[mi][3]),
                          "r"(b0), "r"(b1));
                }
            }
        }

        asm volatile("cp.async.wait_group 1;");
        __syncthreads();
    }
#undef ISSUE

    // epilogue
    #pragma unroll
    for (int mi = 0; mi < 2; mi++) {
        const int r = bm + wm + mi * 16 + (lane >> 2);
        #pragma unroll
        for (int ni = 0; ni < 8; ni++) {
            const int col = bn + wn + ni * 8 + 2 * (lane & 3);
            const float bv0 = bias[col];
            const float bv1 = bias[col + 1];
            #pragma unroll
            for (int h = 0; h < 2; h++) {
                const int m = r + h * 8;
                float v0 = acc[mi][ni][h * 2 + 0] + bv0;
                float v1 = acc[mi][ni][h * 2 + 1] + bv1;
                if (RELU) { v0 = fmaxf(v0, 0.0f); v1 = fmaxf(v1, 0.0f); }
                if (SWAP) {
                    const int c = m >> 9;
                    const int l = m & 511;
                    if (OUTBF) {
                        __nv_bfloat16* Cb = (__nv_bfloat16*)Cout;
                        Cb[((size_t)c * DCP + col) * LSEQ + l]     = __float2bfloat16(v0);
                        Cb[((size_t)c * DCP + col + 1) * LSEQ + l] = __float2bfloat16(v1);
                    } else {
                        float* Cf = (float*)Cout;
                        Cf[((size_t)c * DCP + col) * LSEQ + l]     = v0;
                        Cf[((size_t)c * DCP + col + 1) * LSEQ + l] = v1;
                    }
                } else {
                    if (OUTBF) {
                        *(uint32_t*)((__nv_bfloat16*)Cout + (size_t)m * N + col) = packbf(v0, v1);
                    } else {
                        *(float2*)((float*)Cout + (size_t)m * N + col) = make_float2(v0, v1);
                    }
                }
            }
        }
    }
}

// ---------------------------------------------------------------------------
// Fused tail: gather K rows, L1 scores, softmax, weighted sum, gated blend.
// ---------------------------------------------------------------------------
__global__ __launch_bounds__(256) void fuse_k(const float* __restrict__ x_loc,
                                              const float* __restrict__ map_st,
                                              const int*   __restrict__ indices,
                                              const float* __restrict__ lamda1,
                                              const float* __restrict__ lamda2,
                                              float* __restrict__ out)
{
    __shared__ float xs[LSEQ];
    __shared__ float ms[KSEL][LSEQ];
    __shared__ float warpsum[KSEL][8];
    __shared__ float wgt[KSEL];

    const int bc = blockIdx.x;
    const int c  = bc & (CHN - 1);
    const int t  = threadIdx.x;

    const float* xrow = x_loc + (size_t)bc * LSEQ;
    for (int i = t; i < LSEQ; i += 256) xs[i] = xrow[i];

    #pragma unroll
    for (int k = 0; k < KSEL; k++) {
        const int d = indices[bc * KSEL + k];
        const float* mrow = map_st + ((size_t)c * DCP + d) * LSEQ;
        for (int i = t; i < LSEQ; i += 256) ms[k][i] = mrow[i];
    }
    __syncthreads();

    float part[KSEL];
    #pragma unroll
    for (int k = 0; k < KSEL; k++) part[k] = 0.0f;
    for (int i = t; i < LSEQ; i += 256) {
        const float x = xs[i];
        #pragma unroll
        for (int k = 0; k < KSEL; k++) part[k] += fabsf(x - ms[k][i]);
    }

    const int lane = t & 31, w = t >> 5;
    #pragma unroll
    for (int k = 0; k < KSEL; k++) {
        float v = part[k];
        #pragma unroll
        for (int off = 16; off > 0; off >>= 1)
            v += __shfl_down_sync(0xffffffffu, v, off);
        if (lane == 0) warpsum[k][w] = v;
    }
    __syncthreads();

    if (t < KSEL) {
        float s = 0.0f;
        #pragma unroll
        for (int ww = 0; ww < 8; ww++) s += warpsum[t][ww];
        float score = -s * SCALE;
        float mx = score;
        #pragma unroll
        for (int off = 8; off > 0; off >>= 1)
            mx = fmaxf(mx, __shfl_xor_sync(0x0000ffffu, mx, off));
        float e  = expf(score - mx);
        float se = e;
        #pragma unroll
        for (int off = 8; off > 0; off >>= 1)
            se += __shfl_xor_sync(0x0000ffffu, se, off);
        wgt[t] = e / se;
    }
    __syncthreads();

    const float s1 = 1.0f / (1.0f + expf(-lamda1[c]));
    float* orow = out + (size_t)bc * LSEQ;
    for (int i = t; i < LSEQ; i += 256) {
        float g = 0.0f;
        #pragma unroll
        for (int k = 0; k < KSEL; k++) g = fmaf(wgt[k], ms[k][i], g);
        const float s2  = 1.0f / (1.0f + expf(-lamda2[i]));
        const float lam = s1 * s2;
        orow[i] = g * lam + xs[i] * (1.0f - lam);
    }
}

// ---------------------------------------------------------------------------
static void* symaddr(const void* sym)
{
    void* p = nullptr;
    cudaGetSymbolAddress(&p, sym);
    return p;
}

extern "C" void kernel_launch(void* const* d_in, const int* in_sizes, int n_in,
                              void* d_out, int out_size)
{
    const float* x_loc   = (const float*)d_in[0];
    const float* map_raw = (const float*)d_in[1];
    const float* cp_w1   = (const float*)d_in[2];
    const float* cp_b1   = (const float*)d_in[3];
    const float* cp_w2   = (const float*)d_in[4];
    const float* cp_b2   = (const float*)d_in[5];
    const float* de_w1   = (const float*)d_in[6];
    const float* de_b1   = (const float*)d_in[7];
    const float* de_w2   = (const float*)d_in[8];
    const float* de_b2   = (const float*)d_in[9];
    const float* lamda1  = (const float*)d_in[10];
    const float* lamda2  = (const float*)d_in[11];
    const int*   indices = (const int*)d_in[12];
    float* out = (float*)d_out;

    __nv_bfloat16* mapraw = (__nv_bfloat16*)symaddr(g_mapraw);
    __nv_bfloat16* wcp1   = (__nv_bfloat16*)symaddr(g_wcp1);
    __nv_bfloat16* wcp2   = (__nv_bfloat16*)symaddr(g_wcp2);
    __nv_bfloat16* wde1   = (__nv_bfloat16*)symaddr(g_wde1);
    __nv_bfloat16* wde2   = (__nv_bfloat16*)symaddr(g_wde2);
    __nv_bfloat16* h1b    = (__nv_bfloat16*)symaddr(g_h1b);
    __nv_bfloat16* mapTb  = (__nv_bfloat16*)symaddr(g_mapTb);
    __nv_bfloat16* h2b    = (__nv_bfloat16*)symaddr(g_h2b);
    float*         mapst  = (float*)symaddr(g_mapst);

    const int M1 = CHN * LSEQ;   // 32768
    const int M3 = CHN * DCP;    // 16384

    // Single merged convert (N_CVT_TOT/4/256 = 5216 blocks)
    cvt_all<<<N_CVT_TOT / 4 / 256, 256>>>(map_raw, mapraw, cp_w1, wcp1, cp_w2, wcp2,
                                          de_w1, wde1, de_w2, wde2);

    // GEMM1: (32768,128)@(128,256) + b, relu -> h1 (bf16)
    gemm_bf<true,  false, true ><<<dim3(DCP / BN, M1 / BM), 256>>>(mapraw, wcp1, cp_b1, h1b, M1, DCP, INTER);
    // GEMM2: (32768,256)@(256,256) + b -> mapT (bf16, transposed store)
    gemm_bf<false, true,  true ><<<dim3(DCP / BN, M1 / BM), 256>>>(h1b, wcp2, cp_b2, mapTb, M1, DCP, DCP);
    // GEMM3: (16384,512)@(512,1024) + b, relu -> h2 (bf16)
    gemm_bf<true,  false, true ><<<dim3(DDE / BN, M3 / BM), 256>>>(mapTb, wde1, de_b1, h2b, M3, DDE, LSEQ);
    // GEMM4: (16384,1024)@(1024,512) + b -> mapst (f32)
    gemm_bf<false, false, false><<<dim3(LSEQ / BN, M3 / BM), 256>>>(h2b, wde2, de_b2, mapst, M3, LSEQ, DDE);
    // Fused gather/score/softmax/blend
    fuse_k<<<BATCH * CHN, 256>>>(x_loc, mapst, indices, lamda1, lamda2, out);
}

// round 7
// speedup vs baseline: 5.8428x; 1.0091x over previous
#include <cuda_runtime.h>
#include <cuda_bf16.h>
#include <cstdint>

// Problem constants
#define BATCH 64
#define CHN   64
#define LSEQ  512
#define INTER 128
#define DCP   256
#define DDE   1024
#define KSEL  16
#define SCALE 0.05f

// Scratch (device globals; no runtime allocation)
__device__ __align__(16) __nv_bfloat16 g_mapraw[(size_t)CHN * LSEQ * INTER];
__device__ __align__(16) __nv_bfloat16 g_wcp1[INTER * DCP];
__device__ __align__(16) __nv_bfloat16 g_wcp2[DCP * DCP];
__device__ __align__(16) __nv_bfloat16 g_wde1[LSEQ * DDE];
__device__ __align__(16) __nv_bfloat16 g_wde2[DDE * LSEQ];
__device__ __align__(16) __nv_bfloat16 g_h1b[(size_t)CHN * LSEQ * DCP];
__device__ __align__(16) __nv_bfloat16 g_mapTb[(size_t)CHN * DCP * LSEQ];
__device__ __align__(16) __nv_bfloat16 g_h2b[(size_t)CHN * DCP * DDE];
__device__ float g_mapst[(size_t)CHN * DCP * LSEQ];

__device__ __forceinline__ uint32_t packbf(float lo, float hi) {
    uint32_t r;
    asm("cvt.rn.bf16x2.f32 %0, %1, %2;" : "=r"(r) : "f"(hi), "f"(lo));
    return r;
}

// ---------------------------------------------------------------------------
// Single merged f32->bf16 convert over all 5 tensors.
// ---------------------------------------------------------------------------
#define N_MAPRAW (CHN * LSEQ * INTER)     // 4194304
#define N_WCP1   (INTER * DCP)            // 32768
#define N_WCP2   (DCP * DCP)              // 65536
#define N_WDE1   (LSEQ * DDE)             // 524288
#define N_WDE2   (DDE * LSEQ)             // 524288
#define N_CVT_TOT (N_MAPRAW + N_WCP1 + N_WCP2 + N_WDE1 + N_WDE2)

__global__ void cvt_all(const float* __restrict__ s0, __nv_bfloat16* __restrict__ d0,
                        const float* __restrict__ s1, __nv_bfloat16* __restrict__ d1,
                        const float* __restrict__ s2, __nv_bfloat16* __restrict__ d2,
                        const float* __restrict__ s3, __nv_bfloat16* __restrict__ d3,
                        const float* __restrict__ s4, __nv_bfloat16* __restrict__ d4)
{
    int i = (blockIdx.x * blockDim.x + threadIdx.x) * 4;
    const float* s;
    __nv_bfloat16* d;
    if (i < N_MAPRAW)                          { s = s0; d = d0; }
    else if ((i -= N_MAPRAW) < N_WCP1)         { s = s1; d = d1; }
    else if ((i -= N_WCP1) < N_WCP2)           { s = s2; d = d2; }
    else if ((i -= N_WCP2) < N_WDE1)           { s = s3; d = d3; }
    else          { i -= N_WDE1;                 s = s4; d = d4; }
    float4 v = *(const float4*)(s + i);
    uint2 o;
    o.x = packbf(v.x, v.y);
    o.y = packbf(v.z, v.w);
    *(uint2*)(d + i) = o;
}

// ---------------------------------------------------------------------------
// BF16 tensor-core GEMM, cp.async 3-stage pipeline + ldmatrix, BK=64.
// BM=BN=128, 256 threads, 8 warps 4(M)x2(N), warp tile 32x64.
// Smem A: [stage][m][k] 128B rows, chunk swizzle c ^= m&7.
// Smem B: [stage][k][n] 256B rows, chunk swizzle low3 ^= k&7.
// Fragments: A via ldmatrix.x4, B via ldmatrix.x4.trans.
// ---------------------------------------------------------------------------
#define BM 128
#define BN 128
#define BK 64
#define STAGES 3
#define ASTAGE 16384
#define BSTAGE 16384
#define GSMEM (STAGES * (ASTAGE + BSTAGE))   // 98304

__device__ __forceinline__ void cpasync16(uint32_t saddr, const void* gaddr) {
    asm volatile("cp.async.cg.shared.global [%0], [%1], 16;" :: "r"(saddr), "l"(gaddr));
}
__device__ __forceinline__ void ldsm4(uint32_t& r0, uint32_t& r1, uint32_t& r2, uint32_t& r3, uint32_t a) {
    asm volatile("ldmatrix.sync.aligned.m8n8.x4.shared.b16 {%0,%1,%2,%3}, [%4];"
                 : "=r"(r0), "=r"(r1), "=r"(r2), "=r"(r3) : "r"(a));
}
__device__ __forceinline__ void ldsm4t(uint32_t& r0, uint32_t& r1, uint32_t& r2, uint32_t& r3, uint32_t a) {
    asm volatile("ldmatrix.sync.aligned.m8n8.x4.trans.shared.b16 {%0,%1,%2,%3}, [%4];"
                 : "=r"(r0), "=r"(r1), "=r"(r2), "=r"(r3) : "r"(a));
}

template<bool RELU, bool SWAP, bool OUTBF>
__global__ __launch_bounds__(256, 2) void gemm_bf(const __nv_bfloat16* __restrict__ A,
                                                  const __nv_bfloat16* __restrict__ B,
                                                  const float* __restrict__ bias,
                                                  void* __restrict__ Cout,
                                                  int M, int N, int K)
{
    extern __shared__ __align__(16) char smem[];
    const uint32_t sA = (uint32_t)__cvta_generic_to_shared(smem);
    const uint32_t sB = sA + STAGES * ASTAGE;

    const int t    = threadIdx.x;
    const int lane = t & 31;
    const int w    = t >> 5;
    const int wm   = (w & 3) * 32;
    const int wn   = (w >> 2) * 64;
    const int bm   = blockIdx.y * BM;
    const int bn   = blockIdx.x * BN;

    const int ntiles = K / BK;

    // cp.async: A tile = 1024 16B-chunks (row=q>>3, c=q&7), B tile = 1024 (k=q>>4, c=q&15)
#define ISSUE(kt)                                                                     \
    do {                                                                              \
        if ((kt) < ntiles) {                                                          \
            const uint32_t ab = sA + (uint32_t)((kt) % STAGES) * ASTAGE;              \
            const uint32_t bb = sB + (uint32_t)((kt) % STAGES) * BSTAGE;              \
            _Pragma("unroll")                                                         \
            for (int q4 = 0; q4 < 4; q4++) {                                          \
                const int qa   = t + q4 * 256;                                        \
                const int arow = qa >> 3;                                             \
                const int acc_ = qa & 7;                                              \
                const uint32_t aoff = (uint32_t)((arow * 8 + (acc_ ^ (arow & 7))) * 16); \
                cpasync16(ab + aoff,                                                  \
                          A + (size_t)(bm + arow) * K + (kt) * BK + acc_ * 8);        \
                const int bk  = qa >> 4;                                              \
                const int bcc = qa & 15;                                              \
                const uint32_t boff = (uint32_t)((bk * 16 + ((bcc & 8) | ((bcc & 7) ^ (bk & 7)))) * 16); \
                cpasync16(bb + boff,                                                  \
                          B + (size_t)((kt) * BK + bk) * N + bn + bcc * 8);           \
            }                                                                         \
        }                                                                             \
        asm volatile("cp.async.commit_group;");                                       \
    } while (0)

    float acc[2][8][4];
    #pragma unroll
    for (int i = 0; i < 2; i++)
        #pragma unroll
        for (int j = 0; j < 8; j++)
            #pragma unroll
            for (int q = 0; q < 4; q++) acc[i][j][q] = 0.0f;

    ISSUE(0);
    ISSUE(1);
    asm volatile("cp.async.wait_group 1;");
    __syncthreads();

    for (int kt = 0; kt < ntiles; kt++) {
        ISSUE(kt + 2);

        const uint32_t curA = sA + (uint32_t)(kt % STAGES) * ASTAGE;
        const uint32_t curB = sB + (uint32_t)(kt % STAGES) * BSTAGE;

        #pragma unroll
        for (int ks = 0; ks < 4; ks++) {
            // A fragments: 2 x ldsm.x4 (m16 x k16 each)
            uint32_t af[2][4];
            {
                const int cch = ks * 2 + (lane >> 4);          // 0..7
                #pragma unroll
                for (int mi = 0; mi < 2; mi++) {
                    const int m = wm + mi * 16 + (lane & 15);
                    const uint32_t a = curA + (uint32_t)((m * 8 + (cch ^ (m & 7))) * 16);
                    ldsm4(af[mi][0], af[mi][1], af[mi][2], af[mi][3], a);
                }
            }
            // B fragments: 4 x ldsm.x4.trans (k16 x n16 each)
            uint32_t bf[4][4];
            {
                const int k = ks * 16 + (lane & 7) + 8 * ((lane >> 3) & 1);
                const int nc0 = (wn >> 3) + (lane >> 4);
                #pragma unroll
                for (int j = 0; j < 4; j++) {
                    const int nc = nc0 + 2 * j;
                    const uint32_t swz = (uint32_t)((nc & 8) | ((nc & 7) ^ (k & 7)));
                    const uint32_t a = curB + (uint32_t)(k * 256) + swz * 16;
                    ldsm4t(bf[j][0], bf[j][1], bf[j][2], bf[j][3], a);
                }
            }
            #pragma unroll
            for (int ni = 0; ni < 8; ni++) {
                const uint32_t b0 = bf[ni >> 1][(ni & 1) * 2 + 0];
                const uint32_t b1 = bf[ni >> 1][(ni & 1) * 2 + 1];
                #pragma unroll
                for (int mi = 0; mi < 2; mi++) {
                    asm volatile(
                        "mma.sync.aligned.m16n8k16.row.col.f32.bf16.bf16.f32 "
                        "{%0,%1,%2,%3}, {%4,%5,%6,%7}, {%8,%9}, {%0,%1,%2,%3};"
                        : "+f"(acc[mi][ni][0]), "+f"(acc[mi][ni][1]),
                          "+f"(acc[mi][ni][2]), "+f"(acc[mi][ni][3])
                        : "r"(af[mi][0]), "r"(af[mi][1]), "r"(af[mi][2]), "r"(af[mi][3]),
                          "r"(b0), "r"(b1));
                }
            }
        }

        asm volatile("cp.async.wait_group 1;");
        __syncthreads();
    }
#undef ISSUE

    // epilogue
    #pragma unroll
    for (int mi = 0; mi < 2; mi++) {
        const int r = bm + wm + mi * 16 + (lane >> 2);
        #pragma unroll
        for (int ni = 0; ni < 8; ni++) {
            const int col = bn + wn + ni * 8 + 2 * (lane & 3);
            const float bv0 = bias[col];
            const float bv1 = bias[col + 1];
            #pragma unroll
            for (int h = 0; h < 2; h++) {
                const int m = r + h * 8;
                float v0 = acc[mi][ni][h * 2 + 0] + bv0;
                float v1 = acc[mi][ni][h * 2 + 1] + bv1;
                if (RELU) { v0 = fmaxf(v0, 0.0f); v1 = fmaxf(v1, 0.0f); }
                if (SWAP) {
                    const int c = m >> 9;
                    const int l = m & 511;
                    if (OUTBF) {
                        __nv_bfloat16* Cb = (__nv_bfloat16*)Cout;
                        Cb[((size_t)c * DCP + col) * LSEQ + l]     = __float2bfloat16(v0);
                        Cb[((size_t)c * DCP + col + 1) * LSEQ + l] = __float2bfloat16(v1);
                    } else {
                        float* Cf = (float*)Cout;
                        Cf[((size_t)c * DCP + col) * LSEQ + l]     = v0;
                        Cf[((size_t)c * DCP + col + 1) * LSEQ + l] = v1;
                    }
                } else {
                    if (OUTBF) {
                        *(uint32_t*)((__nv_bfloat16*)Cout + (size_t)m * N + col) = packbf(v0, v1);
                    } else {
                        *(float2*)((float*)Cout + (size_t)m * N + col) = make_float2(v0, v1);
                    }
                }
            }
        }
    }
}

// ---------------------------------------------------------------------------
// Fused tail: gather K rows, L1 scores, softmax, weighted sum, gated blend.
// ---------------------------------------------------------------------------
__global__ __launch_bounds__(256) void fuse_k(const float* __restrict__ x_loc,
                                              const float* __restrict__ map_st,
                                              const int*   __restrict__ indices,
                                              const float* __restrict__ lamda1,
                                              const float* __restrict__ lamda2,
                                              float* __restrict__ out)
{
    __shared__ float xs[LSEQ];
    __shared__ float ms[KSEL][LSEQ];
    __shared__ float warpsum[KSEL][8];
    __shared__ float wgt[KSEL];

    const int bc = blockIdx.x;
    const int c  = bc & (CHN - 1);
    const int t  = threadIdx.x;

    const float* xrow = x_loc + (size_t)bc * LSEQ;
    for (int i = t; i < LSEQ; i += 256) xs[i] = xrow[i];

    #pragma unroll
    for (int k = 0; k < KSEL; k++) {
        const int d = indices[bc * KSEL + k];
        const float* mrow = map_st + ((size_t)c * DCP + d) * LSEQ;
        for (int i = t; i < LSEQ; i += 256) ms[k][i] = mrow[i];
    }
    __syncthreads();

    float part[KSEL];
    #pragma unroll
    for (int k = 0; k < KSEL; k++) part[k] = 0.0f;
    for (int i = t; i < LSEQ; i += 256) {
        const float x = xs[i];
        #pragma unroll
        for (int k = 0; k < KSEL; k++) part[k] += fabsf(x - ms[k][i]);
    }

    const int lane = t & 31, w = t >> 5;
    #pragma unroll
    for (int k = 0; k < KSEL; k++) {
        float v = part[k];
        #pragma unroll
        for (int off = 16; off > 0; off >>= 1)
            v += __shfl_down_sync(0xffffffffu, v, off);
        if (lane == 0) warpsum[k][w] = v;
    }
    __syncthreads();

    if (t < KSEL) {
        float s = 0.0f;
        #pragma unroll
        for (int ww = 0; ww < 8; ww++) s += warpsum[t][ww];
        float score = -s * SCALE;
        float mx = score;
        #pragma unroll
        for (int off = 8; off > 0; off >>= 1)
            mx = fmaxf(mx, __shfl_xor_sync(0x0000ffffu, mx, off));
        float e  = expf(score - mx);
        float se = e;
        #pragma unroll
        for (int off = 8; off > 0; off >>= 1)
            se += __shfl_xor_sync(0x0000ffffu, se, off);
        wgt[t] = e / se;
    }
    __syncthreads();

    const float s1 = 1.0f / (1.0f + expf(-lamda1[c]));
    float* orow = out + (size_t)bc * LSEQ;
    for (int i = t; i < LSEQ; i += 256) {
        float g = 0.0f;
        #pragma unroll
        for (int k = 0; k < KSEL; k++) g = fmaf(wgt[k], ms[k][i], g);
        const float s2  = 1.0f / (1.0f + expf(-lamda2[i]));
        const float lam = s1 * s2;
        orow[i] = g * lam + xs[i] * (1.0f - lam);
    }
}

// ---------------------------------------------------------------------------
static void* symaddr(const void* sym)
{
    void* p = nullptr;
    cudaGetSymbolAddress(&p, sym);
    return p;
}

extern "C" void kernel_launch(void* const* d_in, const int* in_sizes, int n_in,
                              void* d_out, int out_size)
{
    const float* x_loc   = (const float*)d_in[0];
    const float* map_raw = (const float*)d_in[1];
    const float* cp_w1   = (const float*)d_in[2];
    const float* cp_b1   = (const float*)d_in[3];
    const float* cp_w2   = (const float*)d_in[4];
    const float* cp_b2   = (const float*)d_in[5];
    const float* de_w1   = (const float*)d_in[6];
    const float* de_b1   = (const float*)d_in[7];
    const float* de_w2   = (const float*)d_in[8];
    const float* de_b2   = (const float*)d_in[9];
    const float* lamda1  = (const float*)d_in[10];
    const float* lamda2  = (const float*)d_in[11];
    const int*   indices = (const int*)d_in[12];
    float* out = (float*)d_out;

    __nv_bfloat16* mapraw = (__nv_bfloat16*)symaddr(g_mapraw);
    __nv_bfloat16* wcp1   = (__nv_bfloat16*)symaddr(g_wcp1);
    __nv_bfloat16* wcp2   = (__nv_bfloat16*)symaddr(g_wcp2);
    __nv_bfloat16* wde1   = (__nv_bfloat16*)symaddr(g_wde1);
    __nv_bfloat16* wde2   = (__nv_bfloat16*)symaddr(g_wde2);
    __nv_bfloat16* h1b    = (__nv_bfloat16*)symaddr(g_h1b);
    __nv_bfloat16* mapTb  = (__nv_bfloat16*)symaddr(g_mapTb);
    __nv_bfloat16* h2b    = (__nv_bfloat16*)symaddr(g_h2b);
    float*         mapst  = (float*)symaddr(g_mapst);

    const int M1 = CHN * LSEQ;   // 32768
    const int M3 = CHN * DCP;    // 16384

    // >48KB dynamic smem opt-in (host-side attribute set; idempotent)
    cudaFuncSetAttribute(gemm_bf<true,  false, true >, cudaFuncAttributeMaxDynamicSharedMemorySize, GSMEM);
    cudaFuncSetAttribute(gemm_bf<false, true,  true >, cudaFuncAttributeMaxDynamicSharedMemorySize, GSMEM);
    cudaFuncSetAttribute(gemm_bf<false, false, false>, cudaFuncAttributeMaxDynamicSharedMemorySize, GSMEM);

    // Single merged convert
    cvt_all<<<N_CVT_TOT / 4 / 256, 256>>>(map_raw, mapraw, cp_w1, wcp1, cp_w2, wcp2,
                                          de_w1, wde1, de_w2, wde2);

    // GEMM1: (32768,128)@(128,256) + b, relu -> h1 (bf16)
    gemm_bf<true,  false, true ><<<dim3(DCP / BN, M1 / BM), 256, GSMEM>>>(mapraw, wcp1, cp_b1, h1b, M1, DCP, INTER);
    // GEMM2: (32768,256)@(256,256) + b -> mapT (bf16, transposed store)
    gemm_bf<false, true,  true ><<<dim3(DCP / BN, M1 / BM), 256, GSMEM>>>(h1b, wcp2, cp_b2, mapTb, M1, DCP, DCP);
    // GEMM3: (16384,512)@(512,1024) + b, relu -> h2 (bf16)
    gemm_bf<true,  false, true ><<<dim3(DDE / BN, M3 / BM), 256, GSMEM>>>(mapTb, wde1, de_b1, h2b, M3, DDE, LSEQ);
    // GEMM4: (16384,1024)@(1024,512) + b -> mapst (f32)
    gemm_bf<false, false, false><<<dim3(LSEQ / BN, M3 / BM), 256, GSMEM>>>(h2b, wde2, de_b2, mapst, M3, LSEQ, DDE);
    // Fused gather/score/softmax/blend
    fuse_k<<<BATCH * CHN, 256>>>(x_loc, mapst, indices, lamda1, lamda2, out);
}

// round 8
// speedup vs baseline: 5.8999x; 1.0098x over previous
#include <cuda_runtime.h>
#include <cuda_bf16.h>
#include <cstdint>

// Problem constants
#define BATCH 64
#define CHN   64
#define LSEQ  512
#define INTER 128
#define DCP   256
#define DDE   1024
#define KSEL  16
#define SCALE 0.05f

// Scratch (device globals; no runtime allocation)
__device__ __align__(16) __nv_bfloat16 g_mapraw[(size_t)CHN * LSEQ * INTER];
__device__ __align__(16) __nv_bfloat16 g_wcp1[INTER * DCP];
__device__ __align__(16) __nv_bfloat16 g_wcp2[DCP * DCP];
__device__ __align__(16) __nv_bfloat16 g_wde1[LSEQ * DDE];
__device__ __align__(16) __nv_bfloat16 g_wde2[DDE * LSEQ];
__device__ __align__(16) __nv_bfloat16 g_h1b[(size_t)CHN * LSEQ * DCP];
__device__ __align__(16) __nv_bfloat16 g_mapTb[(size_t)CHN * DCP * LSEQ];
__device__ __align__(16) __nv_bfloat16 g_h2b[(size_t)CHN * DCP * DDE];
__device__ float g_mapst[(size_t)CHN * DCP * LSEQ];

__device__ __forceinline__ uint32_t packbf(float lo, float hi) {
    uint32_t r;
    asm("cvt.rn.bf16x2.f32 %0, %1, %2;" : "=r"(r) : "f"(hi), "f"(lo));
    return r;
}

// ---------------------------------------------------------------------------
// Single merged f32->bf16 convert over all 5 tensors.
// ---------------------------------------------------------------------------
#define N_MAPRAW (CHN * LSEQ * INTER)     // 4194304
#define N_WCP1   (INTER * DCP)            // 32768
#define N_WCP2   (DCP * DCP)              // 65536
#define N_WDE1   (LSEQ * DDE)             // 524288
#define N_WDE2   (DDE * LSEQ)             // 524288
#define N_CVT_TOT (N_MAPRAW + N_WCP1 + N_WCP2 + N_WDE1 + N_WDE2)

__global__ void cvt_all(const float* __restrict__ s0, __nv_bfloat16* __restrict__ d0,
                        const float* __restrict__ s1, __nv_bfloat16* __restrict__ d1,
                        const float* __restrict__ s2, __nv_bfloat16* __restrict__ d2,
                        const float* __restrict__ s3, __nv_bfloat16* __restrict__ d3,
                        const float* __restrict__ s4, __nv_bfloat16* __restrict__ d4)
{
    int i = (blockIdx.x * blockDim.x + threadIdx.x) * 4;
    const float* s;
    __nv_bfloat16* d;
    if (i < N_MAPRAW)                          { s = s0; d = d0; }
    else if ((i -= N_MAPRAW) < N_WCP1)         { s = s1; d = d1; }
    else if ((i -= N_WCP1) < N_WCP2)           { s = s2; d = d2; }
    else if ((i -= N_WCP2) < N_WDE1)           { s = s3; d = d3; }
    else          { i -= N_WDE1;                 s = s4; d = d4; }
    float4 v = *(const float4*)(s + i);
    uint2 o;
    o.x = packbf(v.x, v.y);
    o.y = packbf(v.z, v.w);
    *(uint2*)(d + i) = o;
}

// ---------------------------------------------------------------------------
// BF16 tensor-core GEMM, cp.async 3-stage pipeline + ldmatrix, BK=64.
// BM=BN=128, 256 threads, 8 warps 4(M)x2(N), warp tile 32x64.
// SWAP epilogue stages through smem for coalesced transposed stores.
// ---------------------------------------------------------------------------
#define BM 128
#define BN 128
#define BK 64
#define STAGES 3
#define ASTAGE 16384
#define BSTAGE 16384
#define GSMEM (STAGES * (ASTAGE + BSTAGE))   // 98304
// SWAP epilogue smem tile: [col][m] bf16, row stride 136 elements (272B = 17*16B)
#define EPI_STRIDE 136

__device__ __forceinline__ void cpasync16(uint32_t saddr, const void* gaddr) {
    asm volatile("cp.async.cg.shared.global [%0], [%1], 16;" :: "r"(saddr), "l"(gaddr));
}
__device__ __forceinline__ void ldsm4(uint32_t& r0, uint32_t& r1, uint32_t& r2, uint32_t& r3, uint32_t a) {
    asm volatile("ldmatrix.sync.aligned.m8n8.x4.shared.b16 {%0,%1,%2,%3}, [%4];"
                 : "=r"(r0), "=r"(r1), "=r"(r2), "=r"(r3) : "r"(a));
}
__device__ __forceinline__ void ldsm4t(uint32_t& r0, uint32_t& r1, uint32_t& r2, uint32_t& r3, uint32_t a) {
    asm volatile("ldmatrix.sync.aligned.m8n8.x4.trans.shared.b16 {%0,%1,%2,%3}, [%4];"
                 : "=r"(r0), "=r"(r1), "=r"(r2), "=r"(r3) : "r"(a));
}

template<bool RELU, bool SWAP, bool OUTBF>
__global__ __launch_bounds__(256, 2) void gemm_bf(const __nv_bfloat16* __restrict__ A,
                                                  const __nv_bfloat16* __restrict__ B,
                                                  const float* __restrict__ bias,
                                                  void* __restrict__ Cout,
                                                  int M, int N, int K)
{
    extern __shared__ __align__(16) char smem[];
    const uint32_t sA = (uint32_t)__cvta_generic_to_shared(smem);
    const uint32_t sB = sA + STAGES * ASTAGE;

    const int t    = threadIdx.x;
    const int lane = t & 31;
    const int w    = t >> 5;
    const int wm   = (w & 3) * 32;
    const int wn   = (w >> 2) * 64;
    const int bm   = blockIdx.y * BM;
    const int bn   = blockIdx.x * BN;

    const int ntiles = K / BK;

#define ISSUE(kt)                                                                     \
    do {                                                                              \
        if ((kt) < ntiles) {                                                          \
            const uint32_t ab = sA + (uint32_t)((kt) % STAGES) * ASTAGE;              \
            const uint32_t bb = sB + (uint32_t)((kt) % STAGES) * BSTAGE;              \
            _Pragma("unroll")                                                         \
            for (int q4 = 0; q4 < 4; q4++) {                                          \
                const int qa   = t + q4 * 256;                                        \
                const int arow = qa >> 3;                                             \
                const int acc_ = qa & 7;                                              \
                const uint32_t aoff = (uint32_t)((arow * 8 + (acc_ ^ (arow & 7))) * 16); \
                cpasync16(ab + aoff,                                                  \
                          A + (size_t)(bm + arow) * K + (kt) * BK + acc_ * 8);        \
                const int bk  = qa >> 4;                                              \
                const int bcc = qa & 15;                                              \
                const uint32_t boff = (uint32_t)((bk * 16 + ((bcc & 8) | ((bcc & 7) ^ (bk & 7)))) * 16); \
                cpasync16(bb + boff,                                                  \
                          B + (size_t)((kt) * BK + bk) * N + bn + bcc * 8);           \
            }                                                                         \
        }                                                                             \
        asm volatile("cp.async.commit_group;");                                       \
    } while (0)

    float acc[2][8][4];
    #pragma unroll
    for (int i = 0; i < 2; i++)
        #pragma unroll
        for (int j = 0; j < 8; j++)
            #pragma unroll
            for (int q = 0; q < 4; q++) acc[i][j][q] = 0.0f;

    ISSUE(0);
    ISSUE(1);
    asm volatile("cp.async.wait_group 1;");
    __syncthreads();

    for (int kt = 0; kt < ntiles; kt++) {
        ISSUE(kt + 2);

        const uint32_t curA = sA + (uint32_t)(kt % STAGES) * ASTAGE;
        const uint32_t curB = sB + (uint32_t)(kt % STAGES) * BSTAGE;

        #pragma unroll
        for (int ks = 0; ks < 4; ks++) {
            uint32_t af[2][4];
            {
                const int cch = ks * 2 + (lane >> 4);
                #pragma unroll
                for (int mi = 0; mi < 2; mi++) {
                    const int m = wm + mi * 16 + (lane & 15);
                    const uint32_t a = curA + (uint32_t)((m * 8 + (cch ^ (m & 7))) * 16);
                    ldsm4(af[mi][0], af[mi][1], af[mi][2], af[mi][3], a);
                }
            }
            uint32_t bf[4][4];
            {
                const int k = ks * 16 + (lane & 7) + 8 * ((lane >> 3) & 1);
                const int nc0 = (wn >> 3) + (lane >> 4);
                #pragma unroll
                for (int j = 0; j < 4; j++) {
                    const int nc = nc0 + 2 * j;
                    const uint32_t swz = (uint32_t)((nc & 8) | ((nc & 7) ^ (k & 7)));
                    const uint32_t a = curB + (uint32_t)(k * 256) + swz * 16;
                    ldsm4t(bf[j][0], bf[j][1], bf[j][2], bf[j][3], a);
                }
            }
            #pragma unroll
            for (int ni = 0; ni < 8; ni++) {
                const uint32_t b0 = bf[ni >> 1][(ni & 1) * 2 + 0];
                const uint32_t b1 = bf[ni >> 1][(ni & 1) * 2 + 1];
                #pragma unroll
                for (int mi = 0; mi < 2; mi++) {
                    asm volatile(
                        "mma.sync.aligned.m16n8k16.row.col.f32.bf16.bf16.f32 "
                        "{%0,%1,%2,%3}, {%4,%5,%6,%7}, {%8,%9}, {%0,%1,%2,%3};"
                        : "+f"(acc[mi][ni][0]), "+f"(acc[mi][ni][1]),
                          "+f"(acc[mi][ni][2]), "+f"(acc[mi][ni][3])
                        : "r"(af[mi][0]), "r"(af[mi][1]), "r"(af[mi][2]), "r"(af[mi][3]),
                          "r"(b0), "r"(b1));
                }
            }
        }

        asm volatile("cp.async.wait_group 1;");
        __syncthreads();
    }
#undef ISSUE

    if (SWAP) {
        // Stage [col][m] bf16 tile in smem, then coalesced stores along l.
        __nv_bfloat16* epi = (__nv_bfloat16*)smem;
        __syncthreads();   // all warps finished reading stage buffers (acc in regs)
        #pragma unroll
        for (int mi = 0; mi < 2; mi++) {
            const int r = wm + mi * 16 + (lane >> 2);
            #pragma unroll
            for (int ni = 0; ni < 8; ni++) {
                const int col = wn + ni * 8 + 2 * (lane & 3);
                const float bv0 = bias[bn + col];
                const float bv1 = bias[bn + col + 1];
                #pragma unroll
                for (int h = 0; h < 2; h++) {
                    const int m = r + h * 8;
                    float v0 = acc[mi][ni][h * 2 + 0] + bv0;
                    float v1 = acc[mi][ni][h * 2 + 1] + bv1;
                    if (RELU) { v0 = fmaxf(v0, 0.0f); v1 = fmaxf(v1, 0.0f); }
                    epi[(size_t)col * EPI_STRIDE + m]       = __float2bfloat16(v0);
                    epi[(size_t)(col + 1) * EPI_STRIDE + m] = __float2bfloat16(v1);
                }
            }
        }
        __syncthreads();
        // Store: out[(c*DCP + bn+col)*512 + (bm&511) + m], 16B chunks, coalesced.
        const int c  = bm >> 9;
        const int l0 = bm & 511;
        __nv_bfloat16* Cb = (__nv_bfloat16*)Cout;
        #pragma unroll
        for (int i = t; i < 128 * 16; i += 256) {
            const int col = i >> 4, chunk = i & 15;
            uint4 v = *(uint4*)(epi + (size_t)col * EPI_STRIDE + chunk * 8);
            *(uint4*)(Cb + ((size_t)c * DCP + bn + col) * LSEQ + l0 + chunk * 8) = v;
        }
    } else {
        #pragma unroll
        for (int mi = 0; mi < 2; mi++) {
            const int r = bm + wm + mi * 16 + (lane >> 2);
            #pragma unroll
            for (int ni = 0; ni < 8; ni++) {
                const int col = bn + wn + ni * 8 + 2 * (lane & 3);
                const float bv0 = bias[col];
                const float bv1 = bias[col + 1];
                #pragma unroll
                for (int h = 0; h < 2; h++) {
                    const int m = r + h * 8;
                    float v0 = acc[mi][ni][h * 2 + 0] + bv0;
                    float v1 = acc[mi][ni][h * 2 + 1] + bv1;
                    if (RELU) { v0 = fmaxf(v0, 0.0f); v1 = fmaxf(v1, 0.0f); }
                    if (OUTBF) {
                        *(uint32_t*)((__nv_bfloat16*)Cout + (size_t)m * N + col) = packbf(v0, v1);
                    } else {
                        *(float2*)((float*)Cout + (size_t)m * N + col) = make_float2(v0, v1);
                    }
                }
            }
        }
    }
}

// ---------------------------------------------------------------------------
// Fused tail: gather K rows, L1 scores, softmax, weighted sum, gated blend.
// ---------------------------------------------------------------------------
__global__ __launch_bounds__(256) void fuse_k(const float* __restrict__ x_loc,
                                              const float* __restrict__ map_st,
                                              const int*   __restrict__ indices,
                                              const float* __restrict__ lamda1,
                                              const float* __restrict__ lamda2,
                                              float* __restrict__ out)
{
    __shared__ float xs[LSEQ];
    __shared__ float ms[KSEL][LSEQ];
    __shared__ float warpsum[KSEL][8];
    __shared__ float wgt[KSEL];

    const int bc = blockIdx.x;
    const int c  = bc & (CHN - 1);
    const int t  = threadIdx.x;

    const float* xrow = x_loc + (size_t)bc * LSEQ;
    for (int i = t; i < LSEQ; i += 256) xs[i] = xrow[i];

    #pragma unroll
    for (int k = 0; k < KSEL; k++) {
        const int d = indices[bc * KSEL + k];
        const float* mrow = map_st + ((size_t)c * DCP + d) * LSEQ;
        for (int i = t; i < LSEQ; i += 256) ms[k][i] = mrow[i];
    }
    __syncthreads();

    float part[KSEL];
    #pragma unroll
    for (int k = 0; k < KSEL; k++) part[k] = 0.0f;
    for (int i = t; i < LSEQ; i += 256) {
        const float x = xs[i];
        #pragma unroll
        for (int k = 0; k < KSEL; k++) part[k] += fabsf(x - ms[k][i]);
    }

    const int lane = t & 31, w = t >> 5;
    #pragma unroll
    for (int k = 0; k < KSEL; k++) {
        float v = part[k];
        #pragma unroll
        for (int off = 16; off > 0; off >>= 1)
            v += __shfl_down_sync(0xffffffffu, v, off);
        if (lane == 0) warpsum[k][w] = v;
    }
    __syncthreads();

    if (t < KSEL) {
        float s = 0.0f;
        #pragma unroll
        for (int ww = 0; ww < 8; ww++) s += warpsum[t][ww];
        float score = -s * SCALE;
        float mx = score;
        #pragma unroll
        for (int off = 8; off > 0; off >>= 1)
            mx = fmaxf(mx, __shfl_xor_sync(0x0000ffffu, mx, off));
        float e  = expf(score - mx);
        float se = e;
        #pragma unroll
        for (int off = 8; off > 0; off >>= 1)
            se += __shfl_xor_sync(0x0000ffffu, se, off);
        wgt[t] = e / se;
    }
    __syncthreads();

    const float s1 = 1.0f / (1.0f + expf(-lamda1[c]));
    float* orow = out + (size_t)bc * LSEQ;
    for (int i = t; i < LSEQ; i += 256) {
        float g = 0.0f;
        #pragma unroll
        for (int k = 0; k < KSEL; k++) g = fmaf(wgt[k], ms[k][i], g);
        const float s2  = 1.0f / (1.0f + expf(-lamda2[i]));
        const float lam = s1 * s2;
        orow[i] = g * lam + xs[i] * (1.0f - lam);
    }
}

// ---------------------------------------------------------------------------
static void* symaddr(const void* sym)
{
    void* p = nullptr;
    cudaGetSymbolAddress(&p, sym);
    return p;
}

extern "C" void kernel_launch(void* const* d_in, const int* in_sizes, int n_in,
                              void* d_out, int out_size)
{
    const float* x_loc   = (const float*)d_in[0];
    const float* map_raw = (const float*)d_in[1];
    const float* cp_w1   = (const float*)d_in[2];
    const float* cp_b1   = (const float*)d_in[3];
    const float* cp_w2   = (const float*)d_in[4];
    const float* cp_b2   = (const float*)d_in[5];
    const float* de_w1   = (const float*)d_in[6];
    const float* de_b1   = (const float*)d_in[7];
    const float* de_w2   = (const float*)d_in[8];
    const float* de_b2   = (const float*)d_in[9];
    const float* lamda1  = (const float*)d_in[10];
    const float* lamda2  = (const float*)d_in[11];
    const int*   indices = (const int*)d_in[12];
    float* out = (float*)d_out;

    __nv_bfloat16* mapraw = (__nv_bfloat16*)symaddr(g_mapraw);
    __nv_bfloat16* wcp1   = (__nv_bfloat16*)symaddr(g_wcp1);
    __nv_bfloat16* wcp2   = (__nv_bfloat16*)symaddr(g_wcp2);
    __nv_bfloat16* wde1   = (__nv_bfloat16*)symaddr(g_wde1);
    __nv_bfloat16* wde2   = (__nv_bfloat16*)symaddr(g_wde2);
    __nv_bfloat16* h1b    = (__nv_bfloat16*)symaddr(g_h1b);
    __nv_bfloat16* mapTb  = (__nv_bfloat16*)symaddr(g_mapTb);
    __nv_bfloat16* h2b    = (__nv_bfloat16*)symaddr(g_h2b);
    float*         mapst  = (float*)symaddr(g_mapst);

    const int M1 = CHN * LSEQ;   // 32768
    const int M3 = CHN * DCP;    // 16384

    cudaFuncSetAttribute(gemm_bf<true,  false, true >, cudaFuncAttributeMaxDynamicSharedMemorySize, GSMEM);
    cudaFuncSetAttribute(gemm_bf<false, true,  true >, cudaFuncAttributeMaxDynamicSharedMemorySize, GSMEM);
    cudaFuncSetAttribute(gemm_bf<false, false, false>, cudaFuncAttributeMaxDynamicSharedMemorySize, GSMEM);

    cvt_all<<<N_CVT_TOT / 4 / 256, 256>>>(map_raw, mapraw, cp_w1, wcp1, cp_w2, wcp2,
                                          de_w1, wde1, de_w2, wde2);

    // GEMM1: (32768,128)@(128,256) + b, relu -> h1 (bf16)
    gemm_bf<true,  false, true ><<<dim3(DCP / BN, M1 / BM), 256, GSMEM>>>(mapraw, wcp1, cp_b1, h1b, M1, DCP, INTER);
    // GEMM2: (32768,256)@(256,256) + b -> mapT (bf16, transposed store via smem)
    gemm_bf<false, true,  true ><<<dim3(DCP / BN, M1 / BM), 256, GSMEM>>>(h1b, wcp2, cp_b2, mapTb, M1, DCP, DCP);
    // GEMM3: (16384,512)@(512,1024) + b, relu -> h2 (bf16)
    gemm_bf<true,  false, true ><<<dim3(DDE / BN, M3 / BM), 256, GSMEM>>>(mapTb, wde1, de_b1, h2b, M3, DDE, LSEQ);
    // GEMM4: (16384,1024)@(1024,512) + b -> mapst (f32)
    gemm_bf<false, false, false><<<dim3(LSEQ / BN, M3 / BM), 256, GSMEM>>>(h2b, wde2, de_b2, mapst, M3, LSEQ, DDE);
    // Fused gather/score/softmax/blend
    fuse_k<<<BATCH * CHN, 256>>>(x_loc, mapst, indices, lamda1, lamda2, out);
}

// round 9
// speedup vs baseline: 6.8903x; 1.1679x over previous
#include <cuda_runtime.h>
#include <cuda_bf16.h>
#include <cstdint>

// Problem constants
#define BATCH 64
#define CHN   64
#define LSEQ  512
#define INTER 128
#define DCP   256
#define DDE   1024
#define KSEL  16
#define SCALE 0.05f

// Scratch (device globals; no runtime allocation)
__device__ __align__(16) __nv_bfloat16 g_mapraw[(size_t)CHN * LSEQ * INTER];
__device__ __align__(16) __nv_bfloat16 g_wcp1[INTER * DCP];
__device__ __align__(16) __nv_bfloat16 g_wcp2[DCP * DCP];
__device__ __align__(16) __nv_bfloat16 g_wde1[LSEQ * DDE];
__device__ __align__(16) __nv_bfloat16 g_wde2[DDE * LSEQ];
__device__ __align__(16) __nv_bfloat16 g_h1b[(size_t)CHN * LSEQ * DCP];
__device__ __align__(16) __nv_bfloat16 g_mapTb[(size_t)CHN * DCP * LSEQ];
__device__ __align__(16) __nv_bfloat16 g_h2b[(size_t)CHN * DCP * DDE];
__device__ __align__(16) __nv_bfloat16 g_mapst[(size_t)CHN * DCP * LSEQ];   // bf16 now

__device__ __forceinline__ uint32_t packbf(float lo, float hi) {
    uint32_t r;
    asm("cvt.rn.bf16x2.f32 %0, %1, %2;" : "=r"(r) : "f"(hi), "f"(lo));
    return r;
}

// ---------------------------------------------------------------------------
// Single merged f32->bf16 convert over all 5 tensors.
// ---------------------------------------------------------------------------
#define N_MAPRAW (CHN * LSEQ * INTER)     // 4194304
#define N_WCP1   (INTER * DCP)            // 32768
#define N_WCP2   (DCP * DCP)              // 65536
#define N_WDE1   (LSEQ * DDE)             // 524288
#define N_WDE2   (DDE * LSEQ)             // 524288
#define N_CVT_TOT (N_MAPRAW + N_WCP1 + N_WCP2 + N_WDE1 + N_WDE2)

__global__ void cvt_all(const float* __restrict__ s0, __nv_bfloat16* __restrict__ d0,
                        const float* __restrict__ s1, __nv_bfloat16* __restrict__ d1,
                        const float* __restrict__ s2, __nv_bfloat16* __restrict__ d2,
                        const float* __restrict__ s3, __nv_bfloat16* __restrict__ d3,
                        const float* __restrict__ s4, __nv_bfloat16* __restrict__ d4)
{
    int i = (blockIdx.x * blockDim.x + threadIdx.x) * 4;
    const float* s;
    __nv_bfloat16* d;
    if (i < N_MAPRAW)                          { s = s0; d = d0; }
    else if ((i -= N_MAPRAW) < N_WCP1)         { s = s1; d = d1; }
    else if ((i -= N_WCP1) < N_WCP2)           { s = s2; d = d2; }
    else if ((i -= N_WCP2) < N_WDE1)           { s = s3; d = d3; }
    else          { i -= N_WDE1;                 s = s4; d = d4; }
    float4 v = *(const float4*)(s + i);
    uint2 o;
    o.x = packbf(v.x, v.y);
    o.y = packbf(v.z, v.w);
    *(uint2*)(d + i) = o;
}

// ---------------------------------------------------------------------------
// BF16 tensor-core GEMM, cp.async 3-stage pipeline + ldmatrix, BK=64.
// BM=BN=128, 256 threads, 8 warps 4(M)x2(N), warp tile 32x64.
// SWAP epilogue stages through smem for coalesced transposed stores.
// ---------------------------------------------------------------------------
#define BM 128
#define BN 128
#define BK 64
#define STAGES 3
#define ASTAGE 16384
#define BSTAGE 16384
#define GSMEM (STAGES * (ASTAGE + BSTAGE))   // 98304
#define EPI_STRIDE 136

__device__ __forceinline__ void cpasync16(uint32_t saddr, const void* gaddr) {
    asm volatile("cp.async.cg.shared.global [%0], [%1], 16;" :: "r"(saddr), "l"(gaddr));
}
__device__ __forceinline__ void ldsm4(uint32_t& r0, uint32_t& r1, uint32_t& r2, uint32_t& r3, uint32_t a) {
    asm volatile("ldmatrix.sync.aligned.m8n8.x4.shared.b16 {%0,%1,%2,%3}, [%4];"
                 : "=r"(r0), "=r"(r1), "=r"(r2), "=r"(r3) : "r"(a));
}
__device__ __forceinline__ void ldsm4t(uint32_t& r0, uint32_t& r1, uint32_t& r2, uint32_t& r3, uint32_t a) {
    asm volatile("ldmatrix.sync.aligned.m8n8.x4.trans.shared.b16 {%0,%1,%2,%3}, [%4];"
                 : "=r"(r0), "=r"(r1), "=r"(r2), "=r"(r3) : "r"(a));
}

template<bool RELU, bool SWAP, bool OUTBF>
__global__ __launch_bounds__(256, 2) void gemm_bf(const __nv_bfloat16* __restrict__ A,
                                                  const __nv_bfloat16* __restrict__ B,
                                                  const float* __restrict__ bias,
                                                  void* __restrict__ Cout,
                                                  int M, int N, int K)
{
    extern __shared__ __align__(16) char smem[];
    const uint32_t sA = (uint32_t)__cvta_generic_to_shared(smem);
    const uint32_t sB = sA + STAGES * ASTAGE;

    const int t    = threadIdx.x;
    const int lane = t & 31;
    const int w    = t >> 5;
    const int wm   = (w & 3) * 32;
    const int wn   = (w >> 2) * 64;
    const int bm   = blockIdx.y * BM;
    const int bn   = blockIdx.x * BN;

    const int ntiles = K / BK;

#define ISSUE(kt)                                                                     \
    do {                                                                              \
        if ((kt) < ntiles) {                                                          \
            const uint32_t ab = sA + (uint32_t)((kt) % STAGES) * ASTAGE;              \
            const uint32_t bb = sB + (uint32_t)((kt) % STAGES) * BSTAGE;              \
            _Pragma("unroll")                                                         \
            for (int q4 = 0; q4 < 4; q4++) {                                          \
                const int qa   = t + q4 * 256;                                        \
                const int arow = qa >> 3;                                             \
                const int acc_ = qa & 7;                                              \
                const uint32_t aoff = (uint32_t)((arow * 8 + (acc_ ^ (arow & 7))) * 16); \
                cpasync16(ab + aoff,                                                  \
                          A + (size_t)(bm + arow) * K + (kt) * BK + acc_ * 8);        \
                const int bk  = qa >> 4;                                              \
                const int bcc = qa & 15;                                              \
                const uint32_t boff = (uint32_t)((bk * 16 + ((bcc & 8) | ((bcc & 7) ^ (bk & 7)))) * 16); \
                cpasync16(bb + boff,                                                  \
                          B + (size_t)((kt) * BK + bk) * N + bn + bcc * 8);           \
            }                                                                         \
        }                                                                             \
        asm volatile("cp.async.commit_group;");                                       \
    } while (0)

    float acc[2][8][4];
    #pragma unroll
    for (int i = 0; i < 2; i++)
        #pragma unroll
        for (int j = 0; j < 8; j++)
            #pragma unroll
            for (int q = 0; q < 4; q++) acc[i][j][q] = 0.0f;

    ISSUE(0);
    ISSUE(1);
    asm volatile("cp.async.wait_group 1;");
    __syncthreads();

    for (int kt = 0; kt < ntiles; kt++) {
        ISSUE(kt + 2);

        const uint32_t curA = sA + (uint32_t)(kt % STAGES) * ASTAGE;
        const uint32_t curB = sB + (uint32_t)(kt % STAGES) * BSTAGE;

        #pragma unroll
        for (int ks = 0; ks < 4; ks++) {
            uint32_t af[2][4];
            {
                const int cch = ks * 2 + (lane >> 4);
                #pragma unroll
                for (int mi = 0; mi < 2; mi++) {
                    const int m = wm + mi * 16 + (lane & 15);
                    const uint32_t a = curA + (uint32_t)((m * 8 + (cch ^ (m & 7))) * 16);
                    ldsm4(af[mi][0], af[mi][1], af[mi][2], af[mi][3], a);
                }
            }
            uint32_t bf[4][4];
            {
                const int k = ks * 16 + (lane & 7) + 8 * ((lane >> 3) & 1);
                const int nc0 = (wn >> 3) + (lane >> 4);
                #pragma unroll
                for (int j = 0; j < 4; j++) {
                    const int nc = nc0 + 2 * j;
                    const uint32_t swz = (uint32_t)((nc & 8) | ((nc & 7) ^ (k & 7)));
                    const uint32_t a = curB + (uint32_t)(k * 256) + swz * 16;
                    ldsm4t(bf[j][0], bf[j][1], bf[j][2], bf[j][3], a);
                }
            }
            #pragma unroll
            for (int ni = 0; ni < 8; ni++) {
                const uint32_t b0 = bf[ni >> 1][(ni & 1) * 2 + 0];
                const uint32_t b1 = bf[ni >> 1][(ni & 1) * 2 + 1];
                #pragma unroll
                for (int mi = 0; mi < 2; mi++) {
                    asm volatile(
                        "mma.sync.aligned.m16n8k16.row.col.f32.bf16.bf16.f32 "
                        "{%0,%1,%2,%3}, {%4,%5,%6,%7}, {%8,%9}, {%0,%1,%2,%3};"
                        : "+f"(acc[mi][ni][0]), "+f"(acc[mi][ni][1]),
                          "+f"(acc[mi][ni][2]), "+f"(acc[mi][ni][3])
                        : "r"(af[mi][0]), "r"(af[mi][1]), "r"(af[mi][2]), "r"(af[mi][3]),
                          "r"(b0), "r"(b1));
                }
            }
        }

        asm volatile("cp.async.wait_group 1;");
        __syncthreads();
    }
#undef ISSUE

    if (SWAP) {
        __nv_bfloat16* epi = (__nv_bfloat16*)smem;
        __syncthreads();
        #pragma unroll
        for (int mi = 0; mi < 2; mi++) {
            const int r = wm + mi * 16 + (lane >> 2);
            #pragma unroll
            for (int ni = 0; ni < 8; ni++) {
                const int col = wn + ni * 8 + 2 * (lane & 3);
                const float bv0 = bias[bn + col];
                const float bv1 = bias[bn + col + 1];
                #pragma unroll
                for (int h = 0; h < 2; h++) {
                    const int m = r + h * 8;
                    float v0 = acc[mi][ni][h * 2 + 0] + bv0;
                    float v1 = acc[mi][ni][h * 2 + 1] + bv1;
                    if (RELU) { v0 = fmaxf(v0, 0.0f); v1 = fmaxf(v1, 0.0f); }
                    epi[(size_t)col * EPI_STRIDE + m]       = __float2bfloat16(v0);
                    epi[(size_t)(col + 1) * EPI_STRIDE + m] = __float2bfloat16(v1);
                }
            }
        }
        __syncthreads();
        const int c  = bm >> 9;
        const int l0 = bm & 511;
        __nv_bfloat16* Cb = (__nv_bfloat16*)Cout;
        #pragma unroll
        for (int i = t; i < 128 * 16; i += 256) {
            const int col = i >> 4, chunk = i & 15;
            uint4 v = *(uint4*)(epi + (size_t)col * EPI_STRIDE + chunk * 8);
            *(uint4*)(Cb + ((size_t)c * DCP + bn + col) * LSEQ + l0 + chunk * 8) = v;
        }
    } else {
        #pragma unroll
        for (int mi = 0; mi < 2; mi++) {
            const int r = bm + wm + mi * 16 + (lane >> 2);
            #pragma unroll
            for (int ni = 0; ni < 8; ni++) {
                const int col = bn + wn + ni * 8 + 2 * (lane & 3);
                const float bv0 = bias[col];
                const float bv1 = bias[col + 1];
                #pragma unroll
                for (int h = 0; h < 2; h++) {
                    const int m = r + h * 8;
                    float v0 = acc[mi][ni][h * 2 + 0] + bv0;
                    float v1 = acc[mi][ni][h * 2 + 1] + bv1;
                    if (RELU) { v0 = fmaxf(v0, 0.0f); v1 = fmaxf(v1, 0.0f); }
                    if (OUTBF) {
                        *(uint32_t*)((__nv_bfloat16*)Cout + (size_t)m * N + col) = packbf(v0, v1);
                    } else {
                        *(float2*)((float*)Cout + (size_t)m * N + col) = make_float2(v0, v1);
                    }
                }
            }
        }
    }
}

// ---------------------------------------------------------------------------
// Fused tail: gather K rows (bf16), L1 scores, softmax, weighted sum, blend.
// ---------------------------------------------------------------------------
__global__ __launch_bounds__(256) void fuse_k(const float* __restrict__ x_loc,
                                              const __nv_bfloat16* __restrict__ map_st,
                                              const int*   __restrict__ indices,
                                              const float* __restrict__ lamda1,
                                              const float* __restrict__ lamda2,
                                              float* __restrict__ out)
{
    __shared__ float xs[LSEQ];
    __shared__ __nv_bfloat16 ms[KSEL][LSEQ];
    __shared__ float warpsum[KSEL][8];
    __shared__ float wgt[KSEL];

    const int bc = blockIdx.x;
    const int c  = bc & (CHN - 1);
    const int t  = threadIdx.x;

    const float* xrow = x_loc + (size_t)bc * LSEQ;
    for (int i = t; i < LSEQ; i += 256) xs[i] = xrow[i];

    // gather 16 bf16 rows (each 1KB) via 16B chunks: 64 chunks/row, 1024 total
    #pragma unroll
    for (int q = 0; q < 4; q++) {
        const int idx = t + q * 256;           // 0..1023
        const int k = idx >> 6, chunk = idx & 63;
        const int d = indices[bc * KSEL + k];
        const uint4* src = (const uint4*)(map_st + ((size_t)c * DCP + d) * LSEQ) + chunk;
        ((uint4*)&ms[k][0])[(size_t)0 + chunk + 0] = src[0];   // ms[k] is 512 bf16 = 64 uint4
    }
    __syncthreads();

    float part[KSEL];
    #pragma unroll
    for (int k = 0; k < KSEL; k++) part[k] = 0.0f;
    for (int i = t; i < LSEQ; i += 256) {
        const float x = xs[i];
        #pragma unroll
        for (int k = 0; k < KSEL; k++) part[k] += fabsf(x - __bfloat162float(ms[k][i]));
    }

    const int lane = t & 31, w = t >> 5;
    #pragma unroll
    for (int k = 0; k < KSEL; k++) {
        float v = part[k];
        #pragma unroll
        for (int off = 16; off > 0; off >>= 1)
            v += __shfl_down_sync(0xffffffffu, v, off);
        if (lane == 0) warpsum[k][w] = v;
    }
    __syncthreads();

    if (t < KSEL) {
        float s = 0.0f;
        #pragma unroll
        for (int ww = 0; ww < 8; ww++) s += warpsum[t][ww];
        float score = -s * SCALE;
        float mx = score;
        #pragma unroll
        for (int off = 8; off > 0; off >>= 1)
            mx = fmaxf(mx, __shfl_xor_sync(0x0000ffffu, mx, off));
        float e  = expf(score - mx);
        float se = e;
        #pragma unroll
        for (int off = 8; off > 0; off >>= 1)
            se += __shfl_xor_sync(0x0000ffffu, se, off);
        wgt[t] = e / se;
    }
    __syncthreads();

    const float s1 = 1.0f / (1.0f + expf(-lamda1[c]));
    float* orow = out + (size_t)bc * LSEQ;
    for (int i = t; i < LSEQ; i += 256) {
        float g = 0.0f;
        #pragma unroll
        for (int k = 0; k < KSEL; k++) g = fmaf(wgt[k], __bfloat162float(ms[k][i]), g);
        const float s2  = 1.0f / (1.0f + expf(-lamda2[i]));
        const float lam = s1 * s2;
        orow[i] = g * lam + xs[i] * (1.0f - lam);
    }
}

// ---------------------------------------------------------------------------
static void* symaddr(const void* sym)
{
    void* p = nullptr;
    cudaGetSymbolAddress(&p, sym);
    return p;
}

extern "C" void kernel_launch(void* const* d_in, const int* in_sizes, int n_in,
                              void* d_out, int out_size)
{
    const float* x_loc   = (const float*)d_in[0];
    const float* map_raw = (const float*)d_in[1];
    const float* cp_w1   = (const float*)d_in[2];
    const float* cp_b1   = (const float*)d_in[3];
    const float* cp_w2   = (const float*)d_in[4];
    const float* cp_b2   = (const float*)d_in[5];
    const float* de_w1   = (const float*)d_in[6];
    const float* de_b1   = (const float*)d_in[7];
    const float* de_w2   = (const float*)d_in[8];
    const float* de_b2   = (const float*)d_in[9];
    const float* lamda1  = (const float*)d_in[10];
    const float* lamda2  = (const float*)d_in[11];
    const int*   indices = (const int*)d_in[12];
    float* out = (float*)d_out;

    __nv_bfloat16* mapraw = (__nv_bfloat16*)symaddr(g_mapraw);
    __nv_bfloat16* wcp1   = (__nv_bfloat16*)symaddr(g_wcp1);
    __nv_bfloat16* wcp2   = (__nv_bfloat16*)symaddr(g_wcp2);
    __nv_bfloat16* wde1   = (__nv_bfloat16*)symaddr(g_wde1);
    __nv_bfloat16* wde2   = (__nv_bfloat16*)symaddr(g_wde2);
    __nv_bfloat16* h1b    = (__nv_bfloat16*)symaddr(g_h1b);
    __nv_bfloat16* mapTb  = (__nv_bfloat16*)symaddr(g_mapTb);
    __nv_bfloat16* h2b    = (__nv_bfloat16*)symaddr(g_h2b);
    __nv_bfloat16* mapst  = (__nv_bfloat16*)symaddr(g_mapst);

    const int M1 = CHN * LSEQ;   // 32768
    const int M3 = CHN * DCP;    // 16384

    cudaFuncSetAttribute(gemm_bf<true,  false, true >, cudaFuncAttributeMaxDynamicSharedMemorySize, GSMEM);
    cudaFuncSetAttribute(gemm_bf<false, true,  true >, cudaFuncAttributeMaxDynamicSharedMemorySize, GSMEM);
    cudaFuncSetAttribute(gemm_bf<false, false, true >, cudaFuncAttributeMaxDynamicSharedMemorySize, GSMEM);

    cvt_all<<<N_CVT_TOT / 4 / 256, 256>>>(map_raw, mapraw, cp_w1, wcp1, cp_w2, wcp2,
                                          de_w1, wde1, de_w2, wde2);

    // GEMM1: (32768,128)@(128,256) + b, relu -> h1 (bf16)
    gemm_bf<true,  false, true ><<<dim3(DCP / BN, M1 / BM), 256, GSMEM>>>(mapraw, wcp1, cp_b1, h1b, M1, DCP, INTER);
    // GEMM2: (32768,256)@(256,256) + b -> mapT (bf16, transposed store via smem)
    gemm_bf<false, true,  true ><<<dim3(DCP / BN, M1 / BM), 256, GSMEM>>>(h1b, wcp2, cp_b2, mapTb, M1, DCP, DCP);
    // GEMM3: (16384,512)@(512,1024) + b, relu -> h2 (bf16)
    gemm_bf<true,  false, true ><<<dim3(DDE / BN, M3 / BM), 256, GSMEM>>>(mapTb, wde1, de_b1, h2b, M3, DDE, LSEQ);
    // GEMM4: (16384,1024)@(1024,512) + b -> mapst (bf16 now)
    gemm_bf<false, false, true ><<<dim3(LSEQ / BN, M3 / BM), 256, GSMEM>>>(h2b, wde2, de_b2, mapst, M3, LSEQ, DDE);
    // Fused gather/score/softmax/blend (bf16 map_st)
    fuse_k<<<BATCH * CHN, 256>>>(x_loc, mapst, indices, lamda1, lamda2, out);
}